// round 10
// baseline (speedup 1.0000x reference)
#include <cuda_runtime.h>
#include <math.h>
#include <float.h>

// Fixed problem shapes
#define BB 2
#define VV 3
#define CC 16
#define HH 128
#define WW 160
#define DD 48
#define HWW (HH*WW)            // 20480
#define NPIX (BB*HWW)          // 40960
#define BDHW (BB*DD*HWW)       // 1966080
#define NV (VV-1)              // 2 source views

// Output layout
#define OFF_DEPTH 0
#define OFF_CONF  (NPIX)
#define OFF_PROB  (2*NPIX)
#define OFF_VW    (2*NPIX + BDHW)

// -------- scratch --------
__device__ float g_feat_t[(size_t)BB*VV*HWW*CC];   // [b][v][h][w][c]
__device__ float g_simil[BDHW];
__device__ float g_proj[NV*BB*12];
__device__ float g_reg[28];
// PWL representation of the pixelwise MLP; ab rows padded to 20 floats (bank spread)
__device__ float g_pwl_t[16];
__device__ __align__(16) float g_pwl_ab[17*20];   // row i: alpha[8], beta[8], pad[4]
__device__ float g_pwl_w2[9];

// ======================= prep (row-parallel matrices) =======================
__device__ void compose_proj(const float* p, double* out) {
    const float* E = p;
    const float* K = p + 16;
    for (int i = 0; i < 16; i++) out[i] = (double)E[i];
    for (int r = 0; r < 3; r++)
        for (int c = 0; c < 4; c++) {
            double s = 0.0;
            for (int k = 0; k < 3; k++) s += (double)K[r*4+k] * (double)E[k*4+c];
            out[r*4+c] = s;
        }
}

__global__ void prep_kernel(const float* proj,
                            const float* w0, const float* g0, const float* b0,
                            const float* m0, const float* v0,
                            const float* w1, const float* g1, const float* b1,
                            const float* m1, const float* v1,
                            const float* w2, const float* b2,
                            const float* reg_w, const float* reg_b) {
    __shared__ double sh_comp[BB][VV][16];
    __shared__ double sh_M[BB][4][8];
    __shared__ double sh_refi[BB][16];
    __shared__ float  sh_fw0[16], sh_fc0[16];
    __shared__ float  sh_fw1[8][16], sh_fc1[8];
    __shared__ int    sh_pos[16];

    int tid = threadIdx.x;

    if (tid < BB*VV) {
        int b = tid / VV, v = tid % VV;
        compose_proj(proj + (size_t)(b*VV + v)*2*16, &sh_comp[b][v][0]);
    }
    if (tid >= 32 && tid < 48) {
        int o = tid - 32;
        double s = (double)g0[o] / sqrt((double)v0[o] + 1e-5);
        sh_fw0[o] = (float)((double)w0[o] * s);
        sh_fc0[o] = (float)((double)b0[o] - (double)m0[o] * s);
    }
    if (tid >= 64 && tid < 72) {
        int j = tid - 64;
        double s = (double)g1[j] / sqrt((double)v1[j] + 1e-5);
        for (int o = 0; o < 16; o++)
            sh_fw1[j][o] = (float)((double)w1[j*16+o] * s);
        sh_fc1[j] = (float)((double)b1[j] - (double)m1[j] * s);
        g_pwl_w2[j] = w2[j];
    }
    if (tid == 96) {
        g_pwl_w2[8] = b2[0];
        for (int k = 0; k < 27; k++) g_reg[k] = reg_w[k];
        g_reg[27] = reg_b[0];
    }
    __syncthreads();

    if (tid < BB*4) {
        int b = tid / 4, r = tid % 4;
        for (int j = 0; j < 4; j++) {
            sh_M[b][r][j]   = sh_comp[b][0][r*4+j];
            sh_M[b][r][4+j] = (r == j) ? 1.0 : 0.0;
        }
    }
    __syncthreads();

    for (int col = 0; col < 4; col++) {
        if (tid < BB) {
            int b = tid;
            double pv = sh_M[b][col][col];
            for (int j = 0; j < 8; j++) sh_M[b][col][j] /= pv;
        }
        __syncthreads();
        if (tid < BB*4) {
            int b = tid / 4, r = tid % 4;
            if (r != col) {
                double f = sh_M[b][r][col];
                for (int j = 0; j < 8; j++) sh_M[b][r][j] -= f * sh_M[b][col][j];
            }
        }
        __syncthreads();
    }
    if (tid < BB*16) {
        int b = tid / 16, e = tid % 16;
        sh_refi[b][e] = sh_M[b][e/4][4 + (e & 3)];
    }
    __syncthreads();

    if (tid < NV*BB*12) {
        int e  = tid % 12;
        int vb = tid / 12;
        int b  = vb % BB;
        int v  = 1 + vb / BB;
        int r  = e / 4, c = e & 3;
        double s = 0.0;
        for (int k = 0; k < 4; k++) s += sh_comp[b][v][r*4+k] * sh_refi[b][k*4+c];
        float* dst = g_proj + ((v-1)*BB + b)*12;
        if (c < 3) dst[r*3+c]  = (float)s;
        else       dst[9 + r]  = (float)s;
    }

    if (tid == 0) {
        double t[16]; int ord[16];
        for (int o = 0; o < 16; o++) {
            if (sh_fw0[o] != 0.f) t[o] = -(double)sh_fc0[o] / (double)sh_fw0[o];
            else                  t[o] = DBL_MAX;
            ord[o] = o;
        }
        for (int i = 1; i < 16; i++) {
            int k = ord[i]; double tv = t[k]; int j = i - 1;
            while (j >= 0 && t[ord[j]] > tv) { ord[j+1] = ord[j]; j--; }
            ord[j+1] = k;
        }
        for (int k = 0; k < 16; k++) {
            double tv = t[ord[k]];
            g_pwl_t[k] = (tv >= DBL_MAX) ? FLT_MAX : (float)tv;
            sh_pos[ord[k]] = k;
        }
    }
    __syncthreads();

    if (tid < 17*8) {
        int i = tid / 8;
        int j = tid % 8;
        double alpha = 0.0, beta = (double)sh_fc1[j];
        for (int o = 0; o < 16; o++) {
            bool active;
            float fw0o = sh_fw0[o];
            if (fw0o > 0.f)      active = (sh_pos[o] < i);
            else if (fw0o < 0.f) active = (sh_pos[o] >= i);
            else                 active = (sh_fc0[o] > 0.f);
            if (active) {
                alpha += (double)sh_fw1[j][o] * (double)fw0o;
                beta  += (double)sh_fw1[j][o] * (double)sh_fc0[o];
            }
        }
        g_pwl_ab[i*20 + j]     = (float)alpha;
        g_pwl_ab[i*20 + 8 + j] = (float)beta;
    }
}

// ======================= feature transpose =======================
__global__ void transpose_kernel(const float* __restrict__ feat, int off) {
    int idx = off + blockIdx.x * blockDim.x + threadIdx.x;
    if (idx >= BB*VV*HWW) return;
    int p  = idx % HWW;
    int bv = idx / HWW;
    const float* src = feat + (size_t)bv * CC * HWW + p;
    float v[CC];
#pragma unroll
    for (int c = 0; c < CC; c++) v[c] = src[(size_t)c * HWW];
    float4* dst = (float4*)(g_feat_t + ((size_t)bv * HWW + p) * CC);
    dst[0] = make_float4(v[0],  v[1],  v[2],  v[3]);
    dst[1] = make_float4(v[4],  v[5],  v[6],  v[7]);
    dst[2] = make_float4(v[8],  v[9],  v[10], v[11]);
    dst[3] = make_float4(v[12], v[13], v[14], v[15]);
}

// ======================= helpers =======================
struct Coords {
    float fx, fy;
    int jx0, jy0;
    int ix0, ix1, iy0, iy1;
    float m00, m10, m01, m11;
};
__device__ __forceinline__ Coords proj_coords(float dep, float rx, float ry, float rz,
                                              float tx, float ty, float tz) {
    Coords c;
    float X = fmaf(rx, dep, tx);
    float Y = fmaf(ry, dep, ty);
    float Z = fmaf(rz, dep, tz);
    float px = X / Z;            // exact IEEE division (argmax-sensitive)
    float py = Y / Z;
    float x0f = floorf(px), y0f = floorf(py);
    c.fx = px - x0f; c.fy = py - y0f;
    c.jx0 = __float2int_rd(px);
    c.jy0 = __float2int_rd(py);
    bool bx0 = (c.jx0 >= 0)  && (c.jx0 <  WW);
    bool bx1 = (c.jx0 >= -1) && (c.jx0 <  WW-1);
    bool by0 = (c.jy0 >= 0)  && (c.jy0 <  HH);
    bool by1 = (c.jy0 >= -1) && (c.jy0 <  HH-1);
    c.m00 = (bx0 && by0) ? 1.f : 0.f;
    c.m10 = (bx1 && by0) ? 1.f : 0.f;
    c.m01 = (bx0 && by1) ? 1.f : 0.f;
    c.m11 = (bx1 && by1) ? 1.f : 0.f;
    c.ix0 = min(max(c.jx0,     0), WW-1);
    c.ix1 = min(max(c.jx0 + 1, 0), WW-1);
    c.iy0 = min(max(c.jy0,     0), HH-1);
    c.iy1 = min(max(c.jy0 + 1, 0), HH-1);
    return c;
}

__device__ __forceinline__ float full_dot(const float* fp, const float* rp) {
    float part[4];
#pragma unroll
    for (int qq = 0; qq < 4; qq++) {
        float4 f = ((const float4*)fp)[qq];
        float4 r = ((const float4*)rp)[qq];
        part[qq] = fmaf(f.x, r.x, fmaf(f.y, r.y, fmaf(f.z, r.z, f.w * r.w)));
    }
    return (part[0] + part[1]) + (part[2] + part[3]);
}

// lane q computes part[2q]+part[2q+1]; one shfl_xor(1) gives ((p0+p1)+(p2+p3))
__device__ __forceinline__ float half_dot(const float* fp, int q, float4 ra, float4 rb) {
    const float4* f = (const float4*)fp;
    float4 a = f[2*q], b = f[2*q+1];
    float pa = fmaf(a.x, ra.x, fmaf(a.y, ra.y, fmaf(a.z, ra.z, a.w * ra.w)));
    float pb = fmaf(b.x, rb.x, fmaf(b.y, rb.y, fmaf(b.z, rb.z, b.w * rb.w)));
    return pa + pb;
}

__device__ __forceinline__ float pwl_eval(float s, const float* th, const float* s_ab,
                                          const float* w2r, float fb2) {
    int idx = 0;
#pragma unroll
    for (int i = 0; i < 16; i++) idx += (s > th[i]) ? 1 : 0;
    const float* ab = s_ab + idx * 20;
    float4 A0 = *(const float4*)(ab);
    float4 A1 = *(const float4*)(ab + 4);
    float4 B0 = *(const float4*)(ab + 8);
    float4 B1 = *(const float4*)(ab + 12);
    float ov = fb2;
    ov = fmaf(w2r[0], fmaxf(fmaf(A0.x, s, B0.x), 0.f), ov);
    ov = fmaf(w2r[1], fmaxf(fmaf(A0.y, s, B0.y), 0.f), ov);
    ov = fmaf(w2r[2], fmaxf(fmaf(A0.z, s, B0.z), 0.f), ov);
    ov = fmaf(w2r[3], fmaxf(fmaf(A0.w, s, B0.w), 0.f), ov);
    ov = fmaf(w2r[4], fmaxf(fmaf(A1.x, s, B1.x), 0.f), ov);
    ov = fmaf(w2r[5], fmaxf(fmaf(A1.y, s, B1.y), 0.f), ov);
    ov = fmaf(w2r[6], fmaxf(fmaf(A1.z, s, B1.z), 0.f), ov);
    ov = fmaf(w2r[7], fmaxf(fmaf(A1.w, s, B1.w), 0.f), ov);
    return ov;
}

// ======================= fused main: 2 lanes/pixel, single wave =======================
#define KD (DD/2)   // 24 depths per lane
__global__ void __launch_bounds__(128, 5)
main_kernel(const float* __restrict__ depth_values, float* __restrict__ out) {
    __shared__ __align__(16) float s_ab[17*20];
    for (int i = threadIdx.x; i < 17*20; i += blockDim.x) s_ab[i] = g_pwl_ab[i];
    __syncthreads();

    int tid = blockIdx.x * blockDim.x + threadIdx.x;   // NPIX*2
    int q   = tid & 1;
    int pid = tid >> 1;
    int b = pid / HWW;
    int p = pid - b * HWW;
    int h = p / WW;
    int w = p - h * WW;

    const float* refp = g_feat_t + ((size_t)(b*VV + 0) * HWW + p) * CC;
    float4 ra = ((const float4*)refp)[2*q];
    float4 rb = ((const float4*)refp)[2*q+1];

    float rx[2], ry[2], rz[2], tx[2], ty[2], tz[2];
#pragma unroll
    for (int v = 0; v < 2; v++) {
        const float* pr = g_proj + (v*BB + b) * 12;
        float fw = (float)w, fh = (float)h;
        rx[v] = pr[0]*fw + pr[1]*fh + pr[2];
        ry[v] = pr[3]*fw + pr[4]*fh + pr[5];
        rz[v] = pr[6]*fw + pr[7]*fh + pr[8];
        tx[v] = pr[9]; ty[v] = pr[10]; tz[v] = pr[11];
    }
    const float* src0 = g_feat_t + (size_t)(b*VV + 1) * HWW * CC;
    const float* src1 = g_feat_t + (size_t)(b*VV + 2) * HWW * CC;
    const float* dv   = depth_values + (size_t)b * DD * HWW + p;

    float th[16];
#pragma unroll
    for (int i = 0; i < 16; i++) th[i] = g_pwl_t[i];
    float w2r[8];
#pragma unroll
    for (int j = 0; j < 8; j++) w2r[j] = g_pwl_w2[j];
    float fb2 = g_pwl_w2[8];

    // ---- setup: corner coords at global depth 0 + lane's last depth; coop dots ----
    float dep0  = __ldg(dv);
    float depL  = __ldg(dv + (size_t)(q + 2*(KD-1)) * HWW);
    Coords c0A = proj_coords(dep0, rx[0], ry[0], rz[0], tx[0], ty[0], tz[0]);
    Coords c0B = proj_coords(dep0, rx[1], ry[1], rz[1], tx[1], ty[1], tz[1]);
    Coords cLA = proj_coords(depL, rx[0], ry[0], rz[0], tx[0], ty[0], tz[0]);
    Coords cLB = proj_coords(depL, rx[1], ry[1], rz[1], tx[1], ty[1], tz[1]);

    float dA00 = half_dot(src0 + ((size_t)(c0A.iy0*WW + c0A.ix0)) * CC, q, ra, rb);
    float dA10 = half_dot(src0 + ((size_t)(c0A.iy0*WW + c0A.ix1)) * CC, q, ra, rb);
    float dA01 = half_dot(src0 + ((size_t)(c0A.iy1*WW + c0A.ix0)) * CC, q, ra, rb);
    float dA11 = half_dot(src0 + ((size_t)(c0A.iy1*WW + c0A.ix1)) * CC, q, ra, rb);
    float dB00 = half_dot(src1 + ((size_t)(c0B.iy0*WW + c0B.ix0)) * CC, q, ra, rb);
    float dB10 = half_dot(src1 + ((size_t)(c0B.iy0*WW + c0B.ix1)) * CC, q, ra, rb);
    float dB01 = half_dot(src1 + ((size_t)(c0B.iy1*WW + c0B.ix0)) * CC, q, ra, rb);
    float dB11 = half_dot(src1 + ((size_t)(c0B.iy1*WW + c0B.ix1)) * CC, q, ra, rb);
    dA00 += __shfl_xor_sync(0xffffffffu, dA00, 1);
    dA10 += __shfl_xor_sync(0xffffffffu, dA10, 1);
    dA01 += __shfl_xor_sync(0xffffffffu, dA01, 1);
    dA11 += __shfl_xor_sync(0xffffffffu, dA11, 1);
    dB00 += __shfl_xor_sync(0xffffffffu, dB00, 1);
    dB10 += __shfl_xor_sync(0xffffffffu, dB10, 1);
    dB01 += __shfl_xor_sync(0xffffffffu, dB01, 1);
    dB11 += __shfl_xor_sync(0xffffffffu, dB11, 1);

    bool fast = (c0A.jx0 == cLA.jx0) && (c0A.jy0 == cLA.jy0) &&
                (c0B.jx0 == cLB.jx0) && (c0B.jy0 == cLB.jy0);

    float s0[KD], s1[KD];   // per-lane sims (local memory, lane-interleaved)
    float omax0 = -3.4e38f, omax1 = -3.4e38f;

    const int STR = 2 * HWW;
    const float* dvp = dv + q * HWW;

    if (fast) {
        // corner constant over the whole sweep (px,py monotone in depth):
        // hoist corner floats + masks out of the loop; no branches inside.
        float jxfA = (float)c0A.jx0, jyfA = (float)c0A.jy0;
        float jxfB = (float)c0B.jx0, jyfB = (float)c0B.jy0;
#pragma unroll 1
        for (int k = 0; k < KD; k++) {
            float dep = __ldg(dvp);
            // view 0
            {
                float X = fmaf(rx[0], dep, tx[0]);
                float Y = fmaf(ry[0], dep, ty[0]);
                float Z = fmaf(rz[0], dep, tz[0]);
                float px = X / Z, py = Y / Z;
                float fx = px - jxfA, fy = py - jyfA;
                float w00 = (1.f - fx) * (1.f - fy) * c0A.m00;
                float w10 = fx * (1.f - fy) * c0A.m10;
                float w01 = (1.f - fx) * fy * c0A.m01;
                float w11 = fx * fy * c0A.m11;
                float sim = fmaf(w00, dA00, fmaf(w10, dA10, fmaf(w01, dA01, w11 * dA11))) * 0.0625f;
                s0[k] = sim;
                omax0 = fmaxf(omax0, pwl_eval(sim, th, s_ab, w2r, fb2));
            }
            // view 1
            {
                float X = fmaf(rx[1], dep, tx[1]);
                float Y = fmaf(ry[1], dep, ty[1]);
                float Z = fmaf(rz[1], dep, tz[1]);
                float px = X / Z, py = Y / Z;
                float fx = px - jxfB, fy = py - jyfB;
                float w00 = (1.f - fx) * (1.f - fy) * c0B.m00;
                float w10 = fx * (1.f - fy) * c0B.m10;
                float w01 = (1.f - fx) * fy * c0B.m01;
                float w11 = fx * fy * c0B.m11;
                float sim = fmaf(w00, dB00, fmaf(w10, dB10, fmaf(w01, dB01, w11 * dB11))) * 0.0625f;
                s1[k] = sim;
                omax1 = fmaxf(omax1, pwl_eval(sim, th, s_ab, w2r, fb2));
            }
            dvp += STR;
        }
    } else {
        // general guarded path (rare)
        int cjx0 = c0A.jx0, cjy0 = c0A.jy0, cjx1 = c0B.jx0, cjy1 = c0B.jy0;
#pragma unroll 1
        for (int k = 0; k < KD; k++) {
            float dep = __ldg(dvp);
            {
                Coords c = proj_coords(dep, rx[0], ry[0], rz[0], tx[0], ty[0], tz[0]);
                if (c.jx0 != cjx0 || c.jy0 != cjy0) {
                    cjx0 = c.jx0; cjy0 = c.jy0;
                    dA00 = full_dot(src0 + ((size_t)(c.iy0*WW + c.ix0)) * CC, refp);
                    dA10 = full_dot(src0 + ((size_t)(c.iy0*WW + c.ix1)) * CC, refp);
                    dA01 = full_dot(src0 + ((size_t)(c.iy1*WW + c.ix0)) * CC, refp);
                    dA11 = full_dot(src0 + ((size_t)(c.iy1*WW + c.ix1)) * CC, refp);
                }
                float w00 = (1.f - c.fx) * (1.f - c.fy) * c.m00;
                float w10 = c.fx * (1.f - c.fy) * c.m10;
                float w01 = (1.f - c.fx) * c.fy * c.m01;
                float w11 = c.fx * c.fy * c.m11;
                float sim = fmaf(w00, dA00, fmaf(w10, dA10, fmaf(w01, dA01, w11 * dA11))) * 0.0625f;
                s0[k] = sim;
                omax0 = fmaxf(omax0, pwl_eval(sim, th, s_ab, w2r, fb2));
            }
            {
                Coords c = proj_coords(dep, rx[1], ry[1], rz[1], tx[1], ty[1], tz[1]);
                if (c.jx0 != cjx1 || c.jy0 != cjy1) {
                    cjx1 = c.jx0; cjy1 = c.jy0;
                    dB00 = full_dot(src1 + ((size_t)(c.iy0*WW + c.ix0)) * CC, refp);
                    dB10 = full_dot(src1 + ((size_t)(c.iy0*WW + c.ix1)) * CC, refp);
                    dB01 = full_dot(src1 + ((size_t)(c.iy1*WW + c.ix0)) * CC, refp);
                    dB11 = full_dot(src1 + ((size_t)(c.iy1*WW + c.ix1)) * CC, refp);
                }
                float w00 = (1.f - c.fx) * (1.f - c.fy) * c.m00;
                float w10 = c.fx * (1.f - c.fy) * c.m10;
                float w01 = (1.f - c.fx) * c.fy * c.m01;
                float w11 = c.fx * c.fy * c.m11;
                float sim = fmaf(w00, dB00, fmaf(w10, dB10, fmaf(w01, dB01, w11 * dB11))) * 0.0625f;
                s1[k] = sim;
                omax1 = fmaxf(omax1, pwl_eval(sim, th, s_ab, w2r, fb2));
            }
            dvp += STR;
        }
    }

    omax0 = fmaxf(omax0, __shfl_xor_sync(0xffffffffu, omax0, 1));
    omax1 = fmaxf(omax1, __shfl_xor_sync(0xffffffffu, omax1, 1));

    float vw0 = 1.f / (1.f + expf(-omax0));   // exact sigmoid
    float vw1 = 1.f / (1.f + expf(-omax1));
    if (q == 0) {
        out[OFF_VW + (size_t)b * NV * HWW + p] = vw0;
        out[OFF_VW + (size_t)b * NV * HWW + HWW + p] = vw1;
    }

    float denom = 1e-5f + vw0 + vw1;
    float* sop = g_simil + (size_t)b * DD * HWW + p + q * HWW;
#pragma unroll 1
    for (int k = 0; k < KD; k++) {
        *sop = (s0[k] * vw0 + s1[k] * vw1) / denom;   // exact division
        sop += STR;
    }
}

// ======================= 3x3x3 conv + softmax (4 threads per pixel) =======================
#define DQ (DD/4)   // 12
__global__ void conv_softmax_kernel(const float* __restrict__ depth_values, float* __restrict__ out) {
    __shared__ float s_k[28];
    if (threadIdx.x < 28) s_k[threadIdx.x] = g_reg[threadIdx.x];
    __syncthreads();

    int tid = blockIdx.x * blockDim.x + threadIdx.x;   // NPIX*4
    int q   = tid & 3;
    int pid = tid >> 2;
    int b = pid / HWW;
    int p = pid - b * HWW;
    int h = p / WW;
    int w = p - h * WW;
    int base = q * DQ;

    float c[DQ];
    float bias = s_k[27];
#pragma unroll
    for (int d = 0; d < DQ; d++) c[d] = bias;

    bool wl = (w > 0), wr = (w < WW - 1);
#pragma unroll 1
    for (int dpi = 0; dpi < DQ + 2; dpi++) {
        int dp = base - 1 + dpi;
        if ((unsigned)dp >= (unsigned)DD) continue;
        const float* basep = g_simil + (size_t)(b*DD + dp) * HWW;
        float n[9];
#pragma unroll
        for (int dy = 0; dy < 3; dy++) {
            int hh = h + dy - 1;
            bool vy = (unsigned)hh < (unsigned)HH;
            const float* rowp = basep + hh * WW + w;
            n[dy*3+0] = (vy && wl) ? rowp[-1] : 0.f;
            n[dy*3+1] = vy ? rowp[0] : 0.f;
            n[dy*3+2] = (vy && wr) ? rowp[1] : 0.f;
        }
#pragma unroll
        for (int dz = 0; dz < 3; dz++) {
            int od = dp + 1 - dz;
            int lod = od - base;
            if (lod < 0 || lod >= DQ) continue;
            float acc = 0.f;
#pragma unroll
            for (int i = 0; i < 9; i++) acc = fmaf(s_k[dz*9+i], n[i], acc);
            c[lod] += acc;
        }
    }

    float m = c[0]; int am = base;
#pragma unroll
    for (int d = 1; d < DQ; d++) if (c[d] > m) { m = c[d]; am = base + d; }

#pragma unroll
    for (int mask = 1; mask <= 2; mask <<= 1) {
        float mo  = __shfl_xor_sync(0xffffffffu, m, mask);
        int   amo = __shfl_xor_sync(0xffffffffu, am, mask);
        if (mo > m || (mo == m && amo < am)) { m = mo; am = amo; }
    }

    float sum = 0.f;
#pragma unroll
    for (int d = 0; d < DQ; d++) { float e = __expf(c[d] - m); c[d] = e; sum += e; }
    sum += __shfl_xor_sync(0xffffffffu, sum, 1);
    sum += __shfl_xor_sync(0xffffffffu, sum, 2);
    float inv = __fdividef(1.f, sum);

    float* pp = out + OFF_PROB + (size_t)b * DD * HWW + p;
#pragma unroll
    for (int d = 0; d < DQ; d++) pp[(size_t)(base + d) * HWW] = c[d] * inv;

    if (q == 0) {
        out[OFF_DEPTH + pid] = depth_values[(size_t)b * DD * HWW + (size_t)am * HWW + p];
        out[OFF_CONF + pid] = inv;
    }
}

// ======================= launch =======================
extern "C" void kernel_launch(void* const* d_in, const int* in_sizes, int n_in,
                              void* d_out, int out_size) {
    const float* features     = (const float*)d_in[0];
    const float* proj         = (const float*)d_in[1];
    const float* depth_values = (const float*)d_in[2];
    const float* w0 = (const float*)d_in[3];
    const float* g0 = (const float*)d_in[4];
    const float* b0 = (const float*)d_in[5];
    const float* m0 = (const float*)d_in[6];
    const float* v0 = (const float*)d_in[7];
    const float* w1 = (const float*)d_in[8];
    const float* g1 = (const float*)d_in[9];
    const float* b1 = (const float*)d_in[10];
    const float* m1 = (const float*)d_in[11];
    const float* v1 = (const float*)d_in[12];
    const float* w2 = (const float*)d_in[13];
    const float* b2 = (const float*)d_in[14];
    const float* reg_w = (const float*)d_in[15];
    const float* reg_b = (const float*)d_in[16];
    float* out = (float*)d_out;

    const int TN = BB*VV*HWW;
    const int THALF = TN / 2;        // two transpose launches keep main as launch #4 for ncu

    prep_kernel<<<1, 256>>>(proj, w0, g0, b0, m0, v0, w1, g1, b1, m1, v1, w2, b2, reg_w, reg_b);
    transpose_kernel<<<(THALF + 255) / 256, 256>>>(features, 0);
    transpose_kernel<<<(TN - THALF + 255) / 256, 256>>>(features, THALF);
    main_kernel<<<(NPIX*2) / 128, 128>>>(depth_values, out);
    conv_softmax_kernel<<<(NPIX*4 + 127) / 128, 128>>>(depth_values, out);
}

// round 11
// speedup vs baseline: 1.1419x; 1.1419x over previous
#include <cuda_runtime.h>
#include <math.h>
#include <float.h>

// Fixed problem shapes
#define BB 2
#define VV 3
#define CC 16
#define HH 128
#define WW 160
#define DD 48
#define HWW (HH*WW)            // 20480
#define NPIX (BB*HWW)          // 40960
#define BDHW (BB*DD*HWW)       // 1966080
#define NV (VV-1)              // 2 source views

// Output layout
#define OFF_DEPTH 0
#define OFF_CONF  (NPIX)
#define OFF_PROB  (2*NPIX)
#define OFF_VW    (2*NPIX + BDHW)

// margin (in px units) proving interior floors can't differ from endpoint floors
#define FRAC_MARGIN 2e-4f

// -------- scratch --------
__device__ float g_feat_t[(size_t)BB*VV*HWW*CC];   // [b][v][h][w][c]
__device__ float g_sim[(size_t)NV*BDHW];           // [view][b][d][h][w]
__device__ float g_simil[BDHW];
__device__ float g_proj[NV*BB*12];
__device__ float g_reg[28];
// PWL tables; ab rows padded to 20 floats (bank spread)
__device__ float g_pwl_t[16];
__device__ __align__(16) float g_pwl_ab[17*20];
__device__ float g_pwl_w2[9];

// ======================= prep (row-parallel matrices) =======================
__device__ void compose_proj(const float* p, double* out) {
    const float* E = p;
    const float* K = p + 16;
    for (int i = 0; i < 16; i++) out[i] = (double)E[i];
    for (int r = 0; r < 3; r++)
        for (int c = 0; c < 4; c++) {
            double s = 0.0;
            for (int k = 0; k < 3; k++) s += (double)K[r*4+k] * (double)E[k*4+c];
            out[r*4+c] = s;
        }
}

__global__ void prep_kernel(const float* proj,
                            const float* w0, const float* g0, const float* b0,
                            const float* m0, const float* v0,
                            const float* w1, const float* g1, const float* b1,
                            const float* m1, const float* v1,
                            const float* w2, const float* b2,
                            const float* reg_w, const float* reg_b) {
    __shared__ double sh_comp[BB][VV][16];
    __shared__ double sh_M[BB][4][8];
    __shared__ double sh_refi[BB][16];
    __shared__ float  sh_fw0[16], sh_fc0[16];
    __shared__ float  sh_fw1[8][16], sh_fc1[8];
    __shared__ int    sh_pos[16];

    int tid = threadIdx.x;

    if (tid < BB*VV) {
        int b = tid / VV, v = tid % VV;
        compose_proj(proj + (size_t)(b*VV + v)*2*16, &sh_comp[b][v][0]);
    }
    if (tid >= 32 && tid < 48) {
        int o = tid - 32;
        double s = (double)g0[o] / sqrt((double)v0[o] + 1e-5);
        sh_fw0[o] = (float)((double)w0[o] * s);
        sh_fc0[o] = (float)((double)b0[o] - (double)m0[o] * s);
    }
    if (tid >= 64 && tid < 72) {
        int j = tid - 64;
        double s = (double)g1[j] / sqrt((double)v1[j] + 1e-5);
        for (int o = 0; o < 16; o++)
            sh_fw1[j][o] = (float)((double)w1[j*16+o] * s);
        sh_fc1[j] = (float)((double)b1[j] - (double)m1[j] * s);
        g_pwl_w2[j] = w2[j];
    }
    if (tid == 96) {
        g_pwl_w2[8] = b2[0];
        for (int k = 0; k < 27; k++) g_reg[k] = reg_w[k];
        g_reg[27] = reg_b[0];
    }
    __syncthreads();

    if (tid < BB*4) {
        int b = tid / 4, r = tid % 4;
        for (int j = 0; j < 4; j++) {
            sh_M[b][r][j]   = sh_comp[b][0][r*4+j];
            sh_M[b][r][4+j] = (r == j) ? 1.0 : 0.0;
        }
    }
    __syncthreads();

    for (int col = 0; col < 4; col++) {
        if (tid < BB) {
            int b = tid;
            double pv = sh_M[b][col][col];
            for (int j = 0; j < 8; j++) sh_M[b][col][j] /= pv;
        }
        __syncthreads();
        if (tid < BB*4) {
            int b = tid / 4, r = tid % 4;
            if (r != col) {
                double f = sh_M[b][r][col];
                for (int j = 0; j < 8; j++) sh_M[b][r][j] -= f * sh_M[b][col][j];
            }
        }
        __syncthreads();
    }
    if (tid < BB*16) {
        int b = tid / 16, e = tid % 16;
        sh_refi[b][e] = sh_M[b][e/4][4 + (e & 3)];
    }
    __syncthreads();

    if (tid < NV*BB*12) {
        int e  = tid % 12;
        int vb = tid / 12;
        int b  = vb % BB;
        int v  = 1 + vb / BB;
        int r  = e / 4, c = e & 3;
        double s = 0.0;
        for (int k = 0; k < 4; k++) s += sh_comp[b][v][r*4+k] * sh_refi[b][k*4+c];
        float* dst = g_proj + ((v-1)*BB + b)*12;
        if (c < 3) dst[r*3+c]  = (float)s;
        else       dst[9 + r]  = (float)s;
    }

    if (tid == 0) {
        double t[16]; int ord[16];
        for (int o = 0; o < 16; o++) {
            if (sh_fw0[o] != 0.f) t[o] = -(double)sh_fc0[o] / (double)sh_fw0[o];
            else                  t[o] = DBL_MAX;
            ord[o] = o;
        }
        for (int i = 1; i < 16; i++) {
            int k = ord[i]; double tv = t[k]; int j = i - 1;
            while (j >= 0 && t[ord[j]] > tv) { ord[j+1] = ord[j]; j--; }
            ord[j+1] = k;
        }
        for (int k = 0; k < 16; k++) {
            double tv = t[ord[k]];
            g_pwl_t[k] = (tv >= DBL_MAX) ? FLT_MAX : (float)tv;
            sh_pos[ord[k]] = k;
        }
    }
    __syncthreads();

    if (tid < 17*8) {
        int i = tid / 8;
        int j = tid % 8;
        double alpha = 0.0, beta = (double)sh_fc1[j];
        for (int o = 0; o < 16; o++) {
            bool active;
            float fw0o = sh_fw0[o];
            if (fw0o > 0.f)      active = (sh_pos[o] < i);
            else if (fw0o < 0.f) active = (sh_pos[o] >= i);
            else                 active = (sh_fc0[o] > 0.f);
            if (active) {
                alpha += (double)sh_fw1[j][o] * (double)fw0o;
                beta  += (double)sh_fw1[j][o] * (double)sh_fc0[o];
            }
        }
        g_pwl_ab[i*20 + j]     = (float)alpha;
        g_pwl_ab[i*20 + 8 + j] = (float)beta;
    }
}

// ======================= feature transpose =======================
__global__ void transpose_kernel(const float* __restrict__ feat, int off) {
    int idx = off + blockIdx.x * blockDim.x + threadIdx.x;
    if (idx >= BB*VV*HWW) return;
    int p  = idx % HWW;
    int bv = idx / HWW;
    const float* src = feat + (size_t)bv * CC * HWW + p;
    float v[CC];
#pragma unroll
    for (int c = 0; c < CC; c++) v[c] = src[(size_t)c * HWW];
    float4* dst = (float4*)(g_feat_t + ((size_t)bv * HWW + p) * CC);
    dst[0] = make_float4(v[0],  v[1],  v[2],  v[3]);
    dst[1] = make_float4(v[4],  v[5],  v[6],  v[7]);
    dst[2] = make_float4(v[8],  v[9],  v[10], v[11]);
    dst[3] = make_float4(v[12], v[13], v[14], v[15]);
}

// ======================= helpers =======================
struct Coords {
    float fx, fy;
    int jx0, jy0;
    int ix0, ix1, iy0, iy1;
    float m00, m10, m01, m11;
};
__device__ __forceinline__ Coords proj_coords(float dep, float rx, float ry, float rz,
                                              float tx, float ty, float tz) {
    Coords c;
    float X = fmaf(rx, dep, tx);
    float Y = fmaf(ry, dep, ty);
    float Z = fmaf(rz, dep, tz);
    float px = X / Z;            // exact IEEE division (argmax-sensitive)
    float py = Y / Z;
    float x0f = floorf(px), y0f = floorf(py);
    c.fx = px - x0f; c.fy = py - y0f;
    c.jx0 = __float2int_rd(px);
    c.jy0 = __float2int_rd(py);
    bool bx0 = (c.jx0 >= 0)  && (c.jx0 <  WW);
    bool bx1 = (c.jx0 >= -1) && (c.jx0 <  WW-1);
    bool by0 = (c.jy0 >= 0)  && (c.jy0 <  HH);
    bool by1 = (c.jy0 >= -1) && (c.jy0 <  HH-1);
    c.m00 = (bx0 && by0) ? 1.f : 0.f;
    c.m10 = (bx1 && by0) ? 1.f : 0.f;
    c.m01 = (bx0 && by1) ? 1.f : 0.f;
    c.m11 = (bx1 && by1) ? 1.f : 0.f;
    c.ix0 = min(max(c.jx0,     0), WW-1);
    c.ix1 = min(max(c.jx0 + 1, 0), WW-1);
    c.iy0 = min(max(c.jy0,     0), HH-1);
    c.iy1 = min(max(c.jy0 + 1, 0), HH-1);
    return c;
}

__device__ __forceinline__ float full_dot(const float* fp, const float* rp) {
    float part[4];
#pragma unroll
    for (int qq = 0; qq < 4; qq++) {
        float4 f = ((const float4*)fp)[qq];
        float4 r = ((const float4*)rp)[qq];
        part[qq] = fmaf(f.x, r.x, fmaf(f.y, r.y, fmaf(f.z, r.z, f.w * r.w)));
    }
    return (part[0] + part[1]) + (part[2] + part[3]);
}

__device__ __forceinline__ float quarter_dot(const float* fp, int q, float4 rq) {
    float4 f = ((const float4*)fp)[q];
    return fmaf(f.x, rq.x, fmaf(f.y, rq.y, fmaf(f.z, rq.z, f.w * rq.w)));
}

__device__ __forceinline__ float pwl_eval(float s, const float* th, const float* s_ab,
                                          const float* w2r, float fb2) {
    int idx = 0;
#pragma unroll
    for (int i = 0; i < 16; i++) idx += (s > th[i]) ? 1 : 0;
    const float* ab = s_ab + idx * 20;
    float4 A0 = *(const float4*)(ab);
    float4 A1 = *(const float4*)(ab + 4);
    float4 B0 = *(const float4*)(ab + 8);
    float4 B1 = *(const float4*)(ab + 12);
    float ov = fb2;
    ov = fmaf(w2r[0], fmaxf(fmaf(A0.x, s, B0.x), 0.f), ov);
    ov = fmaf(w2r[1], fmaxf(fmaf(A0.y, s, B0.y), 0.f), ov);
    ov = fmaf(w2r[2], fmaxf(fmaf(A0.z, s, B0.z), 0.f), ov);
    ov = fmaf(w2r[3], fmaxf(fmaf(A0.w, s, B0.w), 0.f), ov);
    ov = fmaf(w2r[4], fmaxf(fmaf(A1.x, s, B1.x), 0.f), ov);
    ov = fmaf(w2r[5], fmaxf(fmaf(A1.y, s, B1.y), 0.f), ov);
    ov = fmaf(w2r[6], fmaxf(fmaf(A1.z, s, B1.z), 0.f), ov);
    ov = fmaf(w2r[7], fmaxf(fmaf(A1.w, s, B1.w), 0.f), ov);
    return ov;
}

// endpoint fracs safely inside (0,1): interior floor provably constant
__device__ __forceinline__ bool frac_safe(float f0, float fL) {
    float lo = fminf(f0, fL), hi = fmaxf(f0, fL);
    return (lo > FRAC_MARGIN) && (hi < 1.f - FRAC_MARGIN);
}

// ======================= fused main: 4 lanes/pixel (R9 skeleton + exact fast path) =======================
__global__ void __launch_bounds__(128, 6)
main_kernel(const float* __restrict__ depth_values, float* __restrict__ out) {
    __shared__ __align__(16) float s_ab[17*20];
    for (int i = threadIdx.x; i < 17*20; i += blockDim.x) s_ab[i] = g_pwl_ab[i];
    __syncthreads();

    int tid = blockIdx.x * blockDim.x + threadIdx.x;   // NPIX*4
    int q   = tid & 3;
    int pid = tid >> 2;
    int b = pid / HWW;
    int p = pid - b * HWW;
    int h = p / WW;
    int w = p - h * WW;

    const float* refp = g_feat_t + ((size_t)(b*VV + 0) * HWW + p) * CC;
    float4 rq = ((const float4*)refp)[q];

    float rx[2], ry[2], rz[2], tx[2], ty[2], tz[2];
#pragma unroll
    for (int v = 0; v < 2; v++) {
        const float* pr = g_proj + (v*BB + b) * 12;
        float fw = (float)w, fh = (float)h;
        rx[v] = pr[0]*fw + pr[1]*fh + pr[2];
        ry[v] = pr[3]*fw + pr[4]*fh + pr[5];
        rz[v] = pr[6]*fw + pr[7]*fh + pr[8];
        tx[v] = pr[9]; ty[v] = pr[10]; tz[v] = pr[11];
    }
    const float* src0 = g_feat_t + (size_t)(b*VV + 1) * HWW * CC;
    const float* src1 = g_feat_t + (size_t)(b*VV + 2) * HWW * CC;
    const float* dv   = depth_values + (size_t)b * DD * HWW + p;
    float* sim0out    = g_sim + (size_t)b * DD * HWW + p;
    float* sim1out    = g_sim + (size_t)BDHW + (size_t)b * DD * HWW + p;

    float th[16];
#pragma unroll
    for (int i = 0; i < 16; i++) th[i] = g_pwl_t[i];
    float w2r[8];
#pragma unroll
    for (int j = 0; j < 8; j++) w2r[j] = g_pwl_w2[j];
    float fb2 = g_pwl_w2[8];

    // ---- setup: coords at global d=0 and d=DD-1 (covers all lanes' ranges) ----
    float dep0 = __ldg(dv);
    float depL = __ldg(dv + (size_t)(DD-1) * HWW);
    Coords c0A = proj_coords(dep0, rx[0], ry[0], rz[0], tx[0], ty[0], tz[0]);
    Coords c0B = proj_coords(dep0, rx[1], ry[1], rz[1], tx[1], ty[1], tz[1]);
    Coords cLA = proj_coords(depL, rx[0], ry[0], rz[0], tx[0], ty[0], tz[0]);
    Coords cLB = proj_coords(depL, rx[1], ry[1], rz[1], tx[1], ty[1], tz[1]);

    // cooperative corner dots at depth-0 corner (butterflied to all 4 lanes)
    float dA00 = quarter_dot(src0 + ((size_t)(c0A.iy0*WW + c0A.ix0)) * CC, q, rq);
    float dA10 = quarter_dot(src0 + ((size_t)(c0A.iy0*WW + c0A.ix1)) * CC, q, rq);
    float dA01 = quarter_dot(src0 + ((size_t)(c0A.iy1*WW + c0A.ix0)) * CC, q, rq);
    float dA11 = quarter_dot(src0 + ((size_t)(c0A.iy1*WW + c0A.ix1)) * CC, q, rq);
    float dB00 = quarter_dot(src1 + ((size_t)(c0B.iy0*WW + c0B.ix0)) * CC, q, rq);
    float dB10 = quarter_dot(src1 + ((size_t)(c0B.iy0*WW + c0B.ix1)) * CC, q, rq);
    float dB01 = quarter_dot(src1 + ((size_t)(c0B.iy1*WW + c0B.ix0)) * CC, q, rq);
    float dB11 = quarter_dot(src1 + ((size_t)(c0B.iy1*WW + c0B.ix1)) * CC, q, rq);
#pragma unroll
    for (int m = 1; m <= 2; m <<= 1) {
        dA00 += __shfl_xor_sync(0xffffffffu, dA00, m);
        dA10 += __shfl_xor_sync(0xffffffffu, dA10, m);
        dA01 += __shfl_xor_sync(0xffffffffu, dA01, m);
        dA11 += __shfl_xor_sync(0xffffffffu, dA11, m);
        dB00 += __shfl_xor_sync(0xffffffffu, dB00, m);
        dB10 += __shfl_xor_sync(0xffffffffu, dB10, m);
        dB01 += __shfl_xor_sync(0xffffffffu, dB01, m);
        dB11 += __shfl_xor_sync(0xffffffffu, dB11, m);
    }

    // exact fast-path predicate: corners equal at both global endpoints AND
    // endpoint fracs clear of boundaries by more than the float-rounding wiggle.
    bool fast = (c0A.jx0 == cLA.jx0) && (c0A.jy0 == cLA.jy0) &&
                (c0B.jx0 == cLB.jx0) && (c0B.jy0 == cLB.jy0) &&
                frac_safe(c0A.fx, cLA.fx) && frac_safe(c0A.fy, cLA.fy) &&
                frac_safe(c0B.fx, cLB.fx) && frac_safe(c0B.fy, cLB.fy);

    float omax0 = -3.4e38f, omax1 = -3.4e38f;

    const int STR = 4 * HWW;
    const float* dvp = dv + q * HWW;
    float* s0p = sim0out + q * HWW;
    float* s1p = sim1out + q * HWW;

    if (fast) {
        // branchless: corner floats + masks hoisted (provably constant)
        float jxfA = (float)c0A.jx0, jyfA = (float)c0A.jy0;
        float jxfB = (float)c0B.jx0, jyfB = (float)c0B.jy0;
#pragma unroll 1
        for (int k = 0; k < DD/4; k++) {
            float dep = __ldg(dvp);
            {
                float X = fmaf(rx[0], dep, tx[0]);
                float Y = fmaf(ry[0], dep, ty[0]);
                float Z = fmaf(rz[0], dep, tz[0]);
                float px = X / Z, py = Y / Z;
                float fx = px - jxfA, fy = py - jyfA;
                float w00 = (1.f - fx) * (1.f - fy) * c0A.m00;
                float w10 = fx * (1.f - fy) * c0A.m10;
                float w01 = (1.f - fx) * fy * c0A.m01;
                float w11 = fx * fy * c0A.m11;
                float sim = fmaf(w00, dA00, fmaf(w10, dA10, fmaf(w01, dA01, w11 * dA11))) * 0.0625f;
                *s0p = sim;
                omax0 = fmaxf(omax0, pwl_eval(sim, th, s_ab, w2r, fb2));
            }
            {
                float X = fmaf(rx[1], dep, tx[1]);
                float Y = fmaf(ry[1], dep, ty[1]);
                float Z = fmaf(rz[1], dep, tz[1]);
                float px = X / Z, py = Y / Z;
                float fx = px - jxfB, fy = py - jyfB;
                float w00 = (1.f - fx) * (1.f - fy) * c0B.m00;
                float w10 = fx * (1.f - fy) * c0B.m10;
                float w01 = (1.f - fx) * fy * c0B.m01;
                float w11 = fx * fy * c0B.m11;
                float sim = fmaf(w00, dB00, fmaf(w10, dB10, fmaf(w01, dB01, w11 * dB11))) * 0.0625f;
                *s1p = sim;
                omax1 = fmaxf(omax1, pwl_eval(sim, th, s_ab, w2r, fb2));
            }
            dvp += STR; s0p += STR; s1p += STR;
        }
    } else {
        // guarded general path (rare; matches R9 exactly)
        int cjx0 = c0A.jx0, cjy0 = c0A.jy0, cjx1 = c0B.jx0, cjy1 = c0B.jy0;
#pragma unroll 1
        for (int k = 0; k < DD/4; k++) {
            float dep = __ldg(dvp);
            {
                Coords c = proj_coords(dep, rx[0], ry[0], rz[0], tx[0], ty[0], tz[0]);
                if (c.jx0 != cjx0 || c.jy0 != cjy0) {
                    cjx0 = c.jx0; cjy0 = c.jy0;
                    dA00 = full_dot(src0 + ((size_t)(c.iy0*WW + c.ix0)) * CC, refp);
                    dA10 = full_dot(src0 + ((size_t)(c.iy0*WW + c.ix1)) * CC, refp);
                    dA01 = full_dot(src0 + ((size_t)(c.iy1*WW + c.ix0)) * CC, refp);
                    dA11 = full_dot(src0 + ((size_t)(c.iy1*WW + c.ix1)) * CC, refp);
                }
                float w00 = (1.f - c.fx) * (1.f - c.fy) * c.m00;
                float w10 = c.fx * (1.f - c.fy) * c.m10;
                float w01 = (1.f - c.fx) * c.fy * c.m01;
                float w11 = c.fx * c.fy * c.m11;
                float sim = fmaf(w00, dA00, fmaf(w10, dA10, fmaf(w01, dA01, w11 * dA11))) * 0.0625f;
                *s0p = sim;
                omax0 = fmaxf(omax0, pwl_eval(sim, th, s_ab, w2r, fb2));
            }
            {
                Coords c = proj_coords(dep, rx[1], ry[1], rz[1], tx[1], ty[1], tz[1]);
                if (c.jx0 != cjx1 || c.jy0 != cjy1) {
                    cjx1 = c.jx0; cjy1 = c.jy0;
                    dB00 = full_dot(src1 + ((size_t)(c.iy0*WW + c.ix0)) * CC, refp);
                    dB10 = full_dot(src1 + ((size_t)(c.iy0*WW + c.ix1)) * CC, refp);
                    dB01 = full_dot(src1 + ((size_t)(c.iy1*WW + c.ix0)) * CC, refp);
                    dB11 = full_dot(src1 + ((size_t)(c.iy1*WW + c.ix1)) * CC, refp);
                }
                float w00 = (1.f - c.fx) * (1.f - c.fy) * c.m00;
                float w10 = c.fx * (1.f - c.fy) * c.m10;
                float w01 = (1.f - c.fx) * c.fy * c.m01;
                float w11 = c.fx * c.fy * c.m11;
                float sim = fmaf(w00, dB00, fmaf(w10, dB10, fmaf(w01, dB01, w11 * dB11))) * 0.0625f;
                *s1p = sim;
                omax1 = fmaxf(omax1, pwl_eval(sim, th, s_ab, w2r, fb2));
            }
            dvp += STR; s0p += STR; s1p += STR;
        }
    }

    omax0 = fmaxf(omax0, __shfl_xor_sync(0xffffffffu, omax0, 1));
    omax0 = fmaxf(omax0, __shfl_xor_sync(0xffffffffu, omax0, 2));
    omax1 = fmaxf(omax1, __shfl_xor_sync(0xffffffffu, omax1, 1));
    omax1 = fmaxf(omax1, __shfl_xor_sync(0xffffffffu, omax1, 2));

    float vw0 = 1.f / (1.f + expf(-omax0));   // exact sigmoid
    float vw1 = 1.f / (1.f + expf(-omax1));
    if (q == 0) {
        out[OFF_VW + (size_t)b * NV * HWW + p] = vw0;
        out[OFF_VW + (size_t)b * NV * HWW + HWW + p] = vw1;
    }

    float denom = 1e-5f + vw0 + vw1;
    const float* r0p = sim0out + q * HWW;
    const float* r1p = sim1out + q * HWW;
    float* sop = g_simil + (size_t)b * DD * HWW + p + q * HWW;
#pragma unroll 1
    for (int k = 0; k < DD/4; k++) {
        float sa = *r0p;
        float sb = *r1p;
        *sop = (sa * vw0 + sb * vw1) / denom;   // exact division
        r0p += STR; r1p += STR; sop += STR;
    }
}

// ======================= 3x3x3 conv + softmax (4 threads per pixel) =======================
#define DQ (DD/4)   // 12
__global__ void conv_softmax_kernel(const float* __restrict__ depth_values, float* __restrict__ out) {
    __shared__ float s_k[28];
    if (threadIdx.x < 28) s_k[threadIdx.x] = g_reg[threadIdx.x];
    __syncthreads();

    int tid = blockIdx.x * blockDim.x + threadIdx.x;   // NPIX*4
    int q   = tid & 3;
    int pid = tid >> 2;
    int b = pid / HWW;
    int p = pid - b * HWW;
    int h = p / WW;
    int w = p - h * WW;
    int base = q * DQ;

    float c[DQ];
    float bias = s_k[27];
#pragma unroll
    for (int d = 0; d < DQ; d++) c[d] = bias;

    bool wl = (w > 0), wr = (w < WW - 1);
#pragma unroll 1
    for (int dpi = 0; dpi < DQ + 2; dpi++) {
        int dp = base - 1 + dpi;
        if ((unsigned)dp >= (unsigned)DD) continue;
        const float* basep = g_simil + (size_t)(b*DD + dp) * HWW;
        float n[9];
#pragma unroll
        for (int dy = 0; dy < 3; dy++) {
            int hh = h + dy - 1;
            bool vy = (unsigned)hh < (unsigned)HH;
            const float* rowp = basep + hh * WW + w;
            n[dy*3+0] = (vy && wl) ? rowp[-1] : 0.f;
            n[dy*3+1] = vy ? rowp[0] : 0.f;
            n[dy*3+2] = (vy && wr) ? rowp[1] : 0.f;
        }
#pragma unroll
        for (int dz = 0; dz < 3; dz++) {
            int od = dp + 1 - dz;
            int lod = od - base;
            if (lod < 0 || lod >= DQ) continue;
            float acc = 0.f;
#pragma unroll
            for (int i = 0; i < 9; i++) acc = fmaf(s_k[dz*9+i], n[i], acc);
            c[lod] += acc;
        }
    }

    float m = c[0]; int am = base;
#pragma unroll
    for (int d = 1; d < DQ; d++) if (c[d] > m) { m = c[d]; am = base + d; }

#pragma unroll
    for (int mask = 1; mask <= 2; mask <<= 1) {
        float mo  = __shfl_xor_sync(0xffffffffu, m, mask);
        int   amo = __shfl_xor_sync(0xffffffffu, am, mask);
        if (mo > m || (mo == m && amo < am)) { m = mo; am = amo; }
    }

    float sum = 0.f;
#pragma unroll
    for (int d = 0; d < DQ; d++) { float e = __expf(c[d] - m); c[d] = e; sum += e; }
    sum += __shfl_xor_sync(0xffffffffu, sum, 1);
    sum += __shfl_xor_sync(0xffffffffu, sum, 2);
    float inv = __fdividef(1.f, sum);

    float* pp = out + OFF_PROB + (size_t)b * DD * HWW + p;
#pragma unroll
    for (int d = 0; d < DQ; d++) pp[(size_t)(base + d) * HWW] = c[d] * inv;

    if (q == 0) {
        out[OFF_DEPTH + pid] = depth_values[(size_t)b * DD * HWW + (size_t)am * HWW + p];
        out[OFF_CONF + pid] = inv;
    }
}

// ======================= launch =======================
extern "C" void kernel_launch(void* const* d_in, const int* in_sizes, int n_in,
                              void* d_out, int out_size) {
    const float* features     = (const float*)d_in[0];
    const float* proj         = (const float*)d_in[1];
    const float* depth_values = (const float*)d_in[2];
    const float* w0 = (const float*)d_in[3];
    const float* g0 = (const float*)d_in[4];
    const float* b0 = (const float*)d_in[5];
    const float* m0 = (const float*)d_in[6];
    const float* v0 = (const float*)d_in[7];
    const float* w1 = (const float*)d_in[8];
    const float* g1 = (const float*)d_in[9];
    const float* b1 = (const float*)d_in[10];
    const float* m1 = (const float*)d_in[11];
    const float* v1 = (const float*)d_in[12];
    const float* w2 = (const float*)d_in[13];
    const float* b2 = (const float*)d_in[14];
    const float* reg_w = (const float*)d_in[15];
    const float* reg_b = (const float*)d_in[16];
    float* out = (float*)d_out;

    const int TN = BB*VV*HWW;
    const int THALF = TN / 2;        // two transpose launches keep main as launch #4 for ncu

    prep_kernel<<<1, 256>>>(proj, w0, g0, b0, m0, v0, w1, g1, b1, m1, v1, w2, b2, reg_w, reg_b);
    transpose_kernel<<<(THALF + 255) / 256, 256>>>(features, 0);
    transpose_kernel<<<(TN - THALF + 255) / 256, 256>>>(features, THALF);
    main_kernel<<<(NPIX*4) / 128, 128>>>(depth_values, out);
    conv_softmax_kernel<<<(NPIX*4 + 127) / 128, 128>>>(depth_values, out);
}

// round 12
// speedup vs baseline: 1.2454x; 1.0906x over previous
#include <cuda_runtime.h>
#include <math.h>
#include <float.h>

// Fixed problem shapes
#define BB 2
#define VV 3
#define CC 16
#define HH 128
#define WW 160
#define DD 48
#define HWW (HH*WW)            // 20480
#define NPIX (BB*HWW)          // 40960
#define BDHW (BB*DD*HWW)       // 1966080
#define NV (VV-1)              // 2 source views

// Output layout
#define OFF_DEPTH 0
#define OFF_CONF  (NPIX)
#define OFF_PROB  (2*NPIX)
#define OFF_VW    (2*NPIX + BDHW)

// margin (in px units) proving interior floors can't differ from endpoint floors
#define FRAC_MARGIN 2e-4f

// -------- scratch --------
__device__ float g_feat_t[(size_t)BB*VV*HWW*CC];   // [b][v][h][w][c]
__device__ float g_simil[BDHW];
__device__ float g_proj[NV*BB*12];
__device__ float g_reg[28];
// PWL tables; ab rows padded to 20 floats (bank spread)
__device__ float g_pwl_t[16];
__device__ __align__(16) float g_pwl_ab[17*20];
__device__ float g_pwl_w2[9];

// ======================= prep (fully parallel) =======================
__device__ void compose_proj(const float* p, double* out) {
    const float* E = p;
    const float* K = p + 16;
    for (int i = 0; i < 16; i++) out[i] = (double)E[i];
    for (int r = 0; r < 3; r++)
        for (int c = 0; c < 4; c++) {
            double s = 0.0;
            for (int k = 0; k < 3; k++) s += (double)K[r*4+k] * (double)E[k*4+c];
            out[r*4+c] = s;
        }
}

__global__ void prep_kernel(const float* proj,
                            const float* w0, const float* g0, const float* b0,
                            const float* m0, const float* v0,
                            const float* w1, const float* g1, const float* b1,
                            const float* m1, const float* v1,
                            const float* w2, const float* b2,
                            const float* reg_w, const float* reg_b) {
    __shared__ double sh_comp[BB][VV][16];
    __shared__ double sh_M[BB][4][8];
    __shared__ double sh_refi[BB][16];
    __shared__ double sh_t[16];
    __shared__ float  sh_fw0[16], sh_fc0[16];
    __shared__ float  sh_fw1[8][16], sh_fc1[8];
    __shared__ int    sh_pos[16];

    int tid = threadIdx.x;

    if (tid < BB*VV) {
        int b = tid / VV, v = tid % VV;
        compose_proj(proj + (size_t)(b*VV + v)*2*16, &sh_comp[b][v][0]);
    }
    if (tid >= 32 && tid < 48) {
        int o = tid - 32;
        double s = (double)g0[o] / sqrt((double)v0[o] + 1e-5);
        sh_fw0[o] = (float)((double)w0[o] * s);
        sh_fc0[o] = (float)((double)b0[o] - (double)m0[o] * s);
    }
    if (tid >= 64 && tid < 72) {
        int j = tid - 64;
        double s = (double)g1[j] / sqrt((double)v1[j] + 1e-5);
        for (int o = 0; o < 16; o++)
            sh_fw1[j][o] = (float)((double)w1[j*16+o] * s);
        sh_fc1[j] = (float)((double)b1[j] - (double)m1[j] * s);
        g_pwl_w2[j] = w2[j];
    }
    if (tid >= 96 && tid < 124) {
        int k = tid - 96;
        g_reg[k] = (k < 27) ? reg_w[k] : reg_b[0];
    }
    if (tid == 124) g_pwl_w2[8] = b2[0];
    __syncthreads();

    if (tid < BB*4) {
        int b = tid / 4, r = tid % 4;
        for (int j = 0; j < 4; j++) {
            sh_M[b][r][j]   = sh_comp[b][0][r*4+j];
            sh_M[b][r][4+j] = (r == j) ? 1.0 : 0.0;
        }
    }
    // breakpoints (parallel with matrix work)
    if (tid >= 32 && tid < 48) {
        int o = tid - 32;
        float fw0o = sh_fw0[o];
        sh_t[o] = (fw0o != 0.f) ? (-(double)sh_fc0[o] / (double)fw0o) : DBL_MAX;
    }
    __syncthreads();

    // Gaussian elimination, row-parallel (pivot always diagonal for K*E matrices)
    for (int col = 0; col < 4; col++) {
        if (tid < BB) {
            int b = tid;
            double pv = sh_M[b][col][col];
            for (int j = 0; j < 8; j++) sh_M[b][col][j] /= pv;
        }
        __syncthreads();
        if (tid < BB*4) {
            int b = tid / 4, r = tid % 4;
            if (r != col) {
                double f = sh_M[b][r][col];
                for (int j = 0; j < 8; j++) sh_M[b][r][j] -= f * sh_M[b][col][j];
            }
        }
        __syncthreads();
    }
    if (tid < BB*16) {
        int b = tid / 16, e = tid % 16;
        sh_refi[b][e] = sh_M[b][e/4][4 + (e & 3)];
    }
    // parallel stable rank (== insertion-sort order by (t, index))
    if (tid >= 32 && tid < 48) {
        int o = tid - 32;
        double tv = sh_t[o];
        int pos = 0;
        for (int oo = 0; oo < 16; oo++) {
            double to = sh_t[oo];
            pos += (to < tv || (to == tv && oo < o)) ? 1 : 0;
        }
        sh_pos[o] = pos;
        g_pwl_t[pos] = (tv >= DBL_MAX) ? FLT_MAX : (float)tv;
    }
    __syncthreads();

    if (tid < NV*BB*12) {
        int e  = tid % 12;
        int vb = tid / 12;
        int b  = vb % BB;
        int v  = 1 + vb / BB;
        int r  = e / 4, c = e & 3;
        double s = 0.0;
        for (int k = 0; k < 4; k++) s += sh_comp[b][v][r*4+k] * sh_refi[b][k*4+c];
        float* dst = g_proj + ((v-1)*BB + b)*12;
        if (c < 3) dst[r*3+c]  = (float)s;
        else       dst[9 + r]  = (float)s;
    }

    // parallel PWL table build: one thread per (interval i, unit j)
    if (tid < 17*8) {
        int i = tid / 8;
        int j = tid % 8;
        double alpha = 0.0, beta = (double)sh_fc1[j];
        for (int o = 0; o < 16; o++) {
            bool active;
            float fw0o = sh_fw0[o];
            if (fw0o > 0.f)      active = (sh_pos[o] < i);
            else if (fw0o < 0.f) active = (sh_pos[o] >= i);
            else                 active = (sh_fc0[o] > 0.f);
            if (active) {
                alpha += (double)sh_fw1[j][o] * (double)fw0o;
                beta  += (double)sh_fw1[j][o] * (double)sh_fc0[o];
            }
        }
        g_pwl_ab[i*20 + j]     = (float)alpha;
        g_pwl_ab[i*20 + 8 + j] = (float)beta;
    }
}

// ======================= feature transpose =======================
__global__ void transpose_kernel(const float* __restrict__ feat, int off) {
    int idx = off + blockIdx.x * blockDim.x + threadIdx.x;
    if (idx >= BB*VV*HWW) return;
    int p  = idx % HWW;
    int bv = idx / HWW;
    const float* src = feat + (size_t)bv * CC * HWW + p;
    float v[CC];
#pragma unroll
    for (int c = 0; c < CC; c++) v[c] = src[(size_t)c * HWW];
    float4* dst = (float4*)(g_feat_t + ((size_t)bv * HWW + p) * CC);
    dst[0] = make_float4(v[0],  v[1],  v[2],  v[3]);
    dst[1] = make_float4(v[4],  v[5],  v[6],  v[7]);
    dst[2] = make_float4(v[8],  v[9],  v[10], v[11]);
    dst[3] = make_float4(v[12], v[13], v[14], v[15]);
}

// ======================= helpers =======================
struct Coords {
    float fx, fy;
    int jx0, jy0;
    int ix0, ix1, iy0, iy1;
    float m00, m10, m01, m11;
};
__device__ __forceinline__ Coords proj_coords(float dep, float rx, float ry, float rz,
                                              float tx, float ty, float tz) {
    Coords c;
    float X = fmaf(rx, dep, tx);
    float Y = fmaf(ry, dep, ty);
    float Z = fmaf(rz, dep, tz);
    float px = X / Z;            // exact IEEE division (argmax-sensitive)
    float py = Y / Z;
    float x0f = floorf(px), y0f = floorf(py);
    c.fx = px - x0f; c.fy = py - y0f;
    c.jx0 = __float2int_rd(px);
    c.jy0 = __float2int_rd(py);
    bool bx0 = (c.jx0 >= 0)  && (c.jx0 <  WW);
    bool bx1 = (c.jx0 >= -1) && (c.jx0 <  WW-1);
    bool by0 = (c.jy0 >= 0)  && (c.jy0 <  HH);
    bool by1 = (c.jy0 >= -1) && (c.jy0 <  HH-1);
    c.m00 = (bx0 && by0) ? 1.f : 0.f;
    c.m10 = (bx1 && by0) ? 1.f : 0.f;
    c.m01 = (bx0 && by1) ? 1.f : 0.f;
    c.m11 = (bx1 && by1) ? 1.f : 0.f;
    c.ix0 = min(max(c.jx0,     0), WW-1);
    c.ix1 = min(max(c.jx0 + 1, 0), WW-1);
    c.iy0 = min(max(c.jy0,     0), HH-1);
    c.iy1 = min(max(c.jy0 + 1, 0), HH-1);
    return c;
}

__device__ __forceinline__ float full_dot(const float* fp, const float* rp) {
    float part[4];
#pragma unroll
    for (int qq = 0; qq < 4; qq++) {
        float4 f = ((const float4*)fp)[qq];
        float4 r = ((const float4*)rp)[qq];
        part[qq] = fmaf(f.x, r.x, fmaf(f.y, r.y, fmaf(f.z, r.z, f.w * r.w)));
    }
    return (part[0] + part[1]) + (part[2] + part[3]);
}

__device__ __forceinline__ float quarter_dot(const float* fp, int q, float4 rq) {
    float4 f = ((const float4*)fp)[q];
    return fmaf(f.x, rq.x, fmaf(f.y, rq.y, fmaf(f.z, rq.z, f.w * rq.w)));
}

__device__ __forceinline__ float pwl_eval(float s, const float* th, const float* s_ab,
                                          const float* w2r, float fb2) {
    int idx = 0;
#pragma unroll
    for (int i = 0; i < 16; i++) idx += (s > th[i]) ? 1 : 0;
    const float* ab = s_ab + idx * 20;
    float4 A0 = *(const float4*)(ab);
    float4 A1 = *(const float4*)(ab + 4);
    float4 B0 = *(const float4*)(ab + 8);
    float4 B1 = *(const float4*)(ab + 12);
    float ov = fb2;
    ov = fmaf(w2r[0], fmaxf(fmaf(A0.x, s, B0.x), 0.f), ov);
    ov = fmaf(w2r[1], fmaxf(fmaf(A0.y, s, B0.y), 0.f), ov);
    ov = fmaf(w2r[2], fmaxf(fmaf(A0.z, s, B0.z), 0.f), ov);
    ov = fmaf(w2r[3], fmaxf(fmaf(A0.w, s, B0.w), 0.f), ov);
    ov = fmaf(w2r[4], fmaxf(fmaf(A1.x, s, B1.x), 0.f), ov);
    ov = fmaf(w2r[5], fmaxf(fmaf(A1.y, s, B1.y), 0.f), ov);
    ov = fmaf(w2r[6], fmaxf(fmaf(A1.z, s, B1.z), 0.f), ov);
    ov = fmaf(w2r[7], fmaxf(fmaf(A1.w, s, B1.w), 0.f), ov);
    return ov;
}

__device__ __forceinline__ bool frac_safe(float f0, float fL) {
    float lo = fminf(f0, fL), hi = fmaxf(f0, fL);
    return (lo > FRAC_MARGIN) && (hi < 1.f - FRAC_MARGIN);
}

// ======================= fused main: 4 lanes/pixel, sims in smem =======================
#define KD (DD/4)   // 12 depths per lane
__global__ void __launch_bounds__(128, 6)
main_kernel(const float* __restrict__ depth_values, float* __restrict__ out) {
    __shared__ __align__(16) float s_ab[17*20];
    __shared__ float s_s0[KD*128];   // [k][tid] sims view0
    __shared__ float s_s1[KD*128];   // [k][tid] sims view1
    for (int i = threadIdx.x; i < 17*20; i += blockDim.x) s_ab[i] = g_pwl_ab[i];
    __syncthreads();

    int tidx = threadIdx.x;
    int tid = blockIdx.x * blockDim.x + tidx;   // NPIX*4
    int q   = tid & 3;
    int pid = tid >> 2;
    int b = pid / HWW;
    int p = pid - b * HWW;
    int h = p / WW;
    int w = p - h * WW;

    const float* refp = g_feat_t + ((size_t)(b*VV + 0) * HWW + p) * CC;
    float4 rq = ((const float4*)refp)[q];

    float rx[2], ry[2], rz[2], tx[2], ty[2], tz[2];
#pragma unroll
    for (int v = 0; v < 2; v++) {
        const float* pr = g_proj + (v*BB + b) * 12;
        float fw = (float)w, fh = (float)h;
        rx[v] = pr[0]*fw + pr[1]*fh + pr[2];
        ry[v] = pr[3]*fw + pr[4]*fh + pr[5];
        rz[v] = pr[6]*fw + pr[7]*fh + pr[8];
        tx[v] = pr[9]; ty[v] = pr[10]; tz[v] = pr[11];
    }
    const float* src0 = g_feat_t + (size_t)(b*VV + 1) * HWW * CC;
    const float* src1 = g_feat_t + (size_t)(b*VV + 2) * HWW * CC;
    const float* dv   = depth_values + (size_t)b * DD * HWW + p;

    float th[16];
#pragma unroll
    for (int i = 0; i < 16; i++) th[i] = g_pwl_t[i];
    float w2r[8];
#pragma unroll
    for (int j = 0; j < 8; j++) w2r[j] = g_pwl_w2[j];
    float fb2 = g_pwl_w2[8];

    // ---- setup: coords at global d=0 and d=DD-1 ----
    float dep0 = __ldg(dv);
    float depL = __ldg(dv + (size_t)(DD-1) * HWW);
    Coords c0A = proj_coords(dep0, rx[0], ry[0], rz[0], tx[0], ty[0], tz[0]);
    Coords c0B = proj_coords(dep0, rx[1], ry[1], rz[1], tx[1], ty[1], tz[1]);
    Coords cLA = proj_coords(depL, rx[0], ry[0], rz[0], tx[0], ty[0], tz[0]);
    Coords cLB = proj_coords(depL, rx[1], ry[1], rz[1], tx[1], ty[1], tz[1]);

    // cooperative corner dots at depth-0 corner (butterflied to all 4 lanes)
    float dA00 = quarter_dot(src0 + ((size_t)(c0A.iy0*WW + c0A.ix0)) * CC, q, rq);
    float dA10 = quarter_dot(src0 + ((size_t)(c0A.iy0*WW + c0A.ix1)) * CC, q, rq);
    float dA01 = quarter_dot(src0 + ((size_t)(c0A.iy1*WW + c0A.ix0)) * CC, q, rq);
    float dA11 = quarter_dot(src0 + ((size_t)(c0A.iy1*WW + c0A.ix1)) * CC, q, rq);
    float dB00 = quarter_dot(src1 + ((size_t)(c0B.iy0*WW + c0B.ix0)) * CC, q, rq);
    float dB10 = quarter_dot(src1 + ((size_t)(c0B.iy0*WW + c0B.ix1)) * CC, q, rq);
    float dB01 = quarter_dot(src1 + ((size_t)(c0B.iy1*WW + c0B.ix0)) * CC, q, rq);
    float dB11 = quarter_dot(src1 + ((size_t)(c0B.iy1*WW + c0B.ix1)) * CC, q, rq);
#pragma unroll
    for (int m = 1; m <= 2; m <<= 1) {
        dA00 += __shfl_xor_sync(0xffffffffu, dA00, m);
        dA10 += __shfl_xor_sync(0xffffffffu, dA10, m);
        dA01 += __shfl_xor_sync(0xffffffffu, dA01, m);
        dA11 += __shfl_xor_sync(0xffffffffu, dA11, m);
        dB00 += __shfl_xor_sync(0xffffffffu, dB00, m);
        dB10 += __shfl_xor_sync(0xffffffffu, dB10, m);
        dB01 += __shfl_xor_sync(0xffffffffu, dB01, m);
        dB11 += __shfl_xor_sync(0xffffffffu, dB11, m);
    }

    bool cornerConst = (c0A.jx0 == cLA.jx0) && (c0A.jy0 == cLA.jy0) &&
                       (c0B.jx0 == cLB.jx0) && (c0B.jy0 == cLB.jy0) &&
                       frac_safe(c0A.fx, cLA.fx) && frac_safe(c0A.fy, cLA.fy) &&
                       frac_safe(c0B.fx, cLB.fx) && frac_safe(c0B.fy, cLB.fy);
    bool interior = (c0A.m00 * c0A.m10 * c0A.m01 * c0A.m11 *
                     c0B.m00 * c0B.m10 * c0B.m01 * c0B.m11) == 1.f;
    bool fast = cornerConst && interior;

    float omax0 = -3.4e38f, omax1 = -3.4e38f;

    const int STR = 4 * HWW;
    const float* dvp = dv + q * HWW;

    if (fast) {
        // single-divide bilinear: 16*sim = (d00*Z^2 + (U*e10+V*e01)*Z + U*V*e11)/Z^2
        float jxfA = (float)c0A.jx0, jyfA = (float)c0A.jy0;
        float jxfB = (float)c0B.jx0, jyfB = (float)c0B.jy0;
        float e10A = dA10 - dA00, e01A = dA01 - dA00;
        float e11A = ((dA00 - dA10) - dA01) + dA11;
        float e10B = dB10 - dB00, e01B = dB01 - dB00;
        float e11B = ((dB00 - dB10) - dB01) + dB11;
#pragma unroll 1
        for (int k = 0; k < KD; k++) {
            float dep = __ldg(dvp);
            {
                float Z = fmaf(rz[0], dep, tz[0]);
                float X = fmaf(rx[0], dep, tx[0]);
                float Y = fmaf(ry[0], dep, ty[0]);
                float U = fmaf(-jxfA, Z, X);
                float V = fmaf(-jyfA, Z, Y);
                float Z2 = Z * Z;
                float a = fmaf(U, e10A, V * e01A);
                float num = fmaf(dA00, Z2, fmaf(a, Z, (U * V) * e11A));
                float sim = (num / Z2) * 0.0625f;
                s_s0[k*128 + tidx] = sim;
                omax0 = fmaxf(omax0, pwl_eval(sim, th, s_ab, w2r, fb2));
            }
            {
                float Z = fmaf(rz[1], dep, tz[1]);
                float X = fmaf(rx[1], dep, tx[1]);
                float Y = fmaf(ry[1], dep, ty[1]);
                float U = fmaf(-jxfB, Z, X);
                float V = fmaf(-jyfB, Z, Y);
                float Z2 = Z * Z;
                float a = fmaf(U, e10B, V * e01B);
                float num = fmaf(dB00, Z2, fmaf(a, Z, (U * V) * e11B));
                float sim = (num / Z2) * 0.0625f;
                s_s1[k*128 + tidx] = sim;
                omax1 = fmaxf(omax1, pwl_eval(sim, th, s_ab, w2r, fb2));
            }
            dvp += STR;
        }
    } else {
        // guarded general path (exact reference arithmetic)
        int cjx0 = c0A.jx0, cjy0 = c0A.jy0, cjx1 = c0B.jx0, cjy1 = c0B.jy0;
#pragma unroll 1
        for (int k = 0; k < KD; k++) {
            float dep = __ldg(dvp);
            {
                Coords c = proj_coords(dep, rx[0], ry[0], rz[0], tx[0], ty[0], tz[0]);
                if (c.jx0 != cjx0 || c.jy0 != cjy0) {
                    cjx0 = c.jx0; cjy0 = c.jy0;
                    dA00 = full_dot(src0 + ((size_t)(c.iy0*WW + c.ix0)) * CC, refp);
                    dA10 = full_dot(src0 + ((size_t)(c.iy0*WW + c.ix1)) * CC, refp);
                    dA01 = full_dot(src0 + ((size_t)(c.iy1*WW + c.ix0)) * CC, refp);
                    dA11 = full_dot(src0 + ((size_t)(c.iy1*WW + c.ix1)) * CC, refp);
                }
                float w00 = (1.f - c.fx) * (1.f - c.fy) * c.m00;
                float w10 = c.fx * (1.f - c.fy) * c.m10;
                float w01 = (1.f - c.fx) * c.fy * c.m01;
                float w11 = c.fx * c.fy * c.m11;
                float sim = fmaf(w00, dA00, fmaf(w10, dA10, fmaf(w01, dA01, w11 * dA11))) * 0.0625f;
                s_s0[k*128 + tidx] = sim;
                omax0 = fmaxf(omax0, pwl_eval(sim, th, s_ab, w2r, fb2));
            }
            {
                Coords c = proj_coords(dep, rx[1], ry[1], rz[1], tx[1], ty[1], tz[1]);
                if (c.jx0 != cjx1 || c.jy0 != cjy1) {
                    cjx1 = c.jx0; cjy1 = c.jy0;
                    dB00 = full_dot(src1 + ((size_t)(c.iy0*WW + c.ix0)) * CC, refp);
                    dB10 = full_dot(src1 + ((size_t)(c.iy0*WW + c.ix1)) * CC, refp);
                    dB01 = full_dot(src1 + ((size_t)(c.iy1*WW + c.ix0)) * CC, refp);
                    dB11 = full_dot(src1 + ((size_t)(c.iy1*WW + c.ix1)) * CC, refp);
                }
                float w00 = (1.f - c.fx) * (1.f - c.fy) * c.m00;
                float w10 = c.fx * (1.f - c.fy) * c.m10;
                float w01 = (1.f - c.fx) * c.fy * c.m01;
                float w11 = c.fx * c.fy * c.m11;
                float sim = fmaf(w00, dB00, fmaf(w10, dB10, fmaf(w01, dB01, w11 * dB11))) * 0.0625f;
                s_s1[k*128 + tidx] = sim;
                omax1 = fmaxf(omax1, pwl_eval(sim, th, s_ab, w2r, fb2));
            }
            dvp += STR;
        }
    }

    omax0 = fmaxf(omax0, __shfl_xor_sync(0xffffffffu, omax0, 1));
    omax0 = fmaxf(omax0, __shfl_xor_sync(0xffffffffu, omax0, 2));
    omax1 = fmaxf(omax1, __shfl_xor_sync(0xffffffffu, omax1, 1));
    omax1 = fmaxf(omax1, __shfl_xor_sync(0xffffffffu, omax1, 2));

    float vw0 = 1.f / (1.f + expf(-omax0));   // exact sigmoid
    float vw1 = 1.f / (1.f + expf(-omax1));
    if (q == 0) {
        out[OFF_VW + (size_t)b * NV * HWW + p] = vw0;
        out[OFF_VW + (size_t)b * NV * HWW + HWW + p] = vw1;
    }

    float denom = 1e-5f + vw0 + vw1;
    float* sop = g_simil + (size_t)b * DD * HWW + p + q * HWW;
#pragma unroll 1
    for (int k = 0; k < KD; k++) {
        float sa = s_s0[k*128 + tidx];
        float sb = s_s1[k*128 + tidx];
        *sop = (sa * vw0 + sb * vw1) / denom;   // exact division
        sop += STR;
    }
}

// ======================= 3x3x3 conv + softmax (4 threads per pixel) =======================
#define DQ (DD/4)   // 12
__global__ void conv_softmax_kernel(const float* __restrict__ depth_values, float* __restrict__ out) {
    __shared__ float s_k[28];
    if (threadIdx.x < 28) s_k[threadIdx.x] = g_reg[threadIdx.x];
    __syncthreads();

    int tid = blockIdx.x * blockDim.x + threadIdx.x;   // NPIX*4
    int q   = tid & 3;
    int pid = tid >> 2;
    int b = pid / HWW;
    int p = pid - b * HWW;
    int h = p / WW;
    int w = p - h * WW;
    int base = q * DQ;

    float c[DQ];
    float bias = s_k[27];
#pragma unroll
    for (int d = 0; d < DQ; d++) c[d] = bias;

    bool wl = (w > 0), wr = (w < WW - 1);
#pragma unroll 1
    for (int dpi = 0; dpi < DQ + 2; dpi++) {
        int dp = base - 1 + dpi;
        if ((unsigned)dp >= (unsigned)DD) continue;
        const float* basep = g_simil + (size_t)(b*DD + dp) * HWW;
        float n[9];
#pragma unroll
        for (int dy = 0; dy < 3; dy++) {
            int hh = h + dy - 1;
            bool vy = (unsigned)hh < (unsigned)HH;
            const float* rowp = basep + hh * WW + w;
            n[dy*3+0] = (vy && wl) ? rowp[-1] : 0.f;
            n[dy*3+1] = vy ? rowp[0] : 0.f;
            n[dy*3+2] = (vy && wr) ? rowp[1] : 0.f;
        }
#pragma unroll
        for (int dz = 0; dz < 3; dz++) {
            int od = dp + 1 - dz;
            int lod = od - base;
            if (lod < 0 || lod >= DQ) continue;
            float acc = 0.f;
#pragma unroll
            for (int i = 0; i < 9; i++) acc = fmaf(s_k[dz*9+i], n[i], acc);
            c[lod] += acc;
        }
    }

    float m = c[0]; int am = base;
#pragma unroll
    for (int d = 1; d < DQ; d++) if (c[d] > m) { m = c[d]; am = base + d; }

#pragma unroll
    for (int mask = 1; mask <= 2; mask <<= 1) {
        float mo  = __shfl_xor_sync(0xffffffffu, m, mask);
        int   amo = __shfl_xor_sync(0xffffffffu, am, mask);
        if (mo > m || (mo == m && amo < am)) { m = mo; am = amo; }
    }

    float sum = 0.f;
#pragma unroll
    for (int d = 0; d < DQ; d++) { float e = __expf(c[d] - m); c[d] = e; sum += e; }
    sum += __shfl_xor_sync(0xffffffffu, sum, 1);
    sum += __shfl_xor_sync(0xffffffffu, sum, 2);
    float inv = __fdividef(1.f, sum);

    float* pp = out + OFF_PROB + (size_t)b * DD * HWW + p;
#pragma unroll
    for (int d = 0; d < DQ; d++) pp[(size_t)(base + d) * HWW] = c[d] * inv;

    if (q == 0) {
        out[OFF_DEPTH + pid] = depth_values[(size_t)b * DD * HWW + (size_t)am * HWW + p];
        out[OFF_CONF + pid] = inv;
    }
}

// ======================= launch =======================
extern "C" void kernel_launch(void* const* d_in, const int* in_sizes, int n_in,
                              void* d_out, int out_size) {
    const float* features     = (const float*)d_in[0];
    const float* proj         = (const float*)d_in[1];
    const float* depth_values = (const float*)d_in[2];
    const float* w0 = (const float*)d_in[3];
    const float* g0 = (const float*)d_in[4];
    const float* b0 = (const float*)d_in[5];
    const float* m0 = (const float*)d_in[6];
    const float* v0 = (const float*)d_in[7];
    const float* w1 = (const float*)d_in[8];
    const float* g1 = (const float*)d_in[9];
    const float* b1 = (const float*)d_in[10];
    const float* m1 = (const float*)d_in[11];
    const float* v1 = (const float*)d_in[12];
    const float* w2 = (const float*)d_in[13];
    const float* b2 = (const float*)d_in[14];
    const float* reg_w = (const float*)d_in[15];
    const float* reg_b = (const float*)d_in[16];
    float* out = (float*)d_out;

    const int TN = BB*VV*HWW;
    const int THALF = TN / 2;        // two transpose launches keep main as launch #4 for ncu

    prep_kernel<<<1, 256>>>(proj, w0, g0, b0, m0, v0, w1, g1, b1, m1, v1, w2, b2, reg_w, reg_b);
    transpose_kernel<<<(THALF + 255) / 256, 256>>>(features, 0);
    transpose_kernel<<<(TN - THALF + 255) / 256, 256>>>(features, THALF);
    main_kernel<<<(NPIX*4) / 128, 128>>>(depth_values, out);
    conv_softmax_kernel<<<(NPIX*4 + 127) / 128, 128>>>(depth_values, out);
}

// round 13
// speedup vs baseline: 1.2499x; 1.0036x over previous
#include <cuda_runtime.h>
#include <math.h>
#include <float.h>

// Fixed problem shapes
#define BB 2
#define VV 3
#define CC 16
#define HH 128
#define WW 160
#define DD 48
#define HWW (HH*WW)            // 20480
#define NPIX (BB*HWW)          // 40960
#define BDHW (BB*DD*HWW)       // 1966080
#define NV (VV-1)              // 2 source views

// Output layout
#define OFF_DEPTH 0
#define OFF_CONF  (NPIX)
#define OFF_PROB  (2*NPIX)
#define OFF_VW    (2*NPIX + BDHW)

#define FRAC_MARGIN 2e-4f

// -------- scratch --------
__device__ float g_feat_t[(size_t)BB*VV*HWW*CC];   // [b][v][h][w][c]
__device__ float g_simil[BDHW];
__device__ float g_proj[NV*BB*12];
__device__ float g_reg[28];
__device__ float g_pwl_t[16];
__device__ __align__(16) float g_pwl_ab[17*20];    // row i: alpha[8], beta[8], pad[4]
__device__ float g_pwl_w2[9];

// ======================= prep (fully parallel) =======================
__device__ void compose_proj(const float* p, double* out) {
    const float* E = p;
    const float* K = p + 16;
    for (int i = 0; i < 16; i++) out[i] = (double)E[i];
    for (int r = 0; r < 3; r++)
        for (int c = 0; c < 4; c++) {
            double s = 0.0;
            for (int k = 0; k < 3; k++) s += (double)K[r*4+k] * (double)E[k*4+c];
            out[r*4+c] = s;
        }
}

__global__ void prep_kernel(const float* proj,
                            const float* w0, const float* g0, const float* b0,
                            const float* m0, const float* v0,
                            const float* w1, const float* g1, const float* b1,
                            const float* m1, const float* v1,
                            const float* w2, const float* b2,
                            const float* reg_w, const float* reg_b) {
    __shared__ double sh_comp[BB][VV][16];
    __shared__ double sh_M[BB][4][8];
    __shared__ double sh_refi[BB][16];
    __shared__ double sh_t[16];
    __shared__ float  sh_fw0[16], sh_fc0[16];
    __shared__ float  sh_fw1[8][16], sh_fc1[8];
    __shared__ int    sh_pos[16];

    int tid = threadIdx.x;

    if (tid < BB*VV) {
        int b = tid / VV, v = tid % VV;
        compose_proj(proj + (size_t)(b*VV + v)*2*16, &sh_comp[b][v][0]);
    }
    if (tid >= 32 && tid < 48) {
        int o = tid - 32;
        double s = (double)g0[o] / sqrt((double)v0[o] + 1e-5);
        sh_fw0[o] = (float)((double)w0[o] * s);
        sh_fc0[o] = (float)((double)b0[o] - (double)m0[o] * s);
    }
    if (tid >= 64 && tid < 72) {
        int j = tid - 64;
        double s = (double)g1[j] / sqrt((double)v1[j] + 1e-5);
        for (int o = 0; o < 16; o++)
            sh_fw1[j][o] = (float)((double)w1[j*16+o] * s);
        sh_fc1[j] = (float)((double)b1[j] - (double)m1[j] * s);
        g_pwl_w2[j] = w2[j];
    }
    if (tid >= 96 && tid < 124) {
        int k = tid - 96;
        g_reg[k] = (k < 27) ? reg_w[k] : reg_b[0];
    }
    if (tid == 124) g_pwl_w2[8] = b2[0];
    __syncthreads();

    if (tid < BB*4) {
        int b = tid / 4, r = tid % 4;
        for (int j = 0; j < 4; j++) {
            sh_M[b][r][j]   = sh_comp[b][0][r*4+j];
            sh_M[b][r][4+j] = (r == j) ? 1.0 : 0.0;
        }
    }
    if (tid >= 32 && tid < 48) {
        int o = tid - 32;
        float fw0o = sh_fw0[o];
        sh_t[o] = (fw0o != 0.f) ? (-(double)sh_fc0[o] / (double)fw0o) : DBL_MAX;
    }
    __syncthreads();

    for (int col = 0; col < 4; col++) {
        if (tid < BB) {
            int b = tid;
            double pv = sh_M[b][col][col];
            for (int j = 0; j < 8; j++) sh_M[b][col][j] /= pv;
        }
        __syncthreads();
        if (tid < BB*4) {
            int b = tid / 4, r = tid % 4;
            if (r != col) {
                double f = sh_M[b][r][col];
                for (int j = 0; j < 8; j++) sh_M[b][r][j] -= f * sh_M[b][col][j];
            }
        }
        __syncthreads();
    }
    if (tid < BB*16) {
        int b = tid / 16, e = tid % 16;
        sh_refi[b][e] = sh_M[b][e/4][4 + (e & 3)];
    }
    if (tid >= 32 && tid < 48) {
        int o = tid - 32;
        double tv = sh_t[o];
        int pos = 0;
        for (int oo = 0; oo < 16; oo++) {
            double to = sh_t[oo];
            pos += (to < tv || (to == tv && oo < o)) ? 1 : 0;
        }
        sh_pos[o] = pos;
        g_pwl_t[pos] = (tv >= DBL_MAX) ? FLT_MAX : (float)tv;
    }
    __syncthreads();

    if (tid < NV*BB*12) {
        int e  = tid % 12;
        int vb = tid / 12;
        int b  = vb % BB;
        int v  = 1 + vb / BB;
        int r  = e / 4, c = e & 3;
        double s = 0.0;
        for (int k = 0; k < 4; k++) s += sh_comp[b][v][r*4+k] * sh_refi[b][k*4+c];
        float* dst = g_proj + ((v-1)*BB + b)*12;
        if (c < 3) dst[r*3+c]  = (float)s;
        else       dst[9 + r]  = (float)s;
    }

    if (tid < 17*8) {
        int i = tid / 8;
        int j = tid % 8;
        double alpha = 0.0, beta = (double)sh_fc1[j];
        for (int o = 0; o < 16; o++) {
            bool active;
            float fw0o = sh_fw0[o];
            if (fw0o > 0.f)      active = (sh_pos[o] < i);
            else if (fw0o < 0.f) active = (sh_pos[o] >= i);
            else                 active = (sh_fc0[o] > 0.f);
            if (active) {
                alpha += (double)sh_fw1[j][o] * (double)fw0o;
                beta  += (double)sh_fw1[j][o] * (double)sh_fc0[o];
            }
        }
        g_pwl_ab[i*20 + j]     = (float)alpha;
        g_pwl_ab[i*20 + 8 + j] = (float)beta;
    }
}

// ======================= feature transpose =======================
__global__ void transpose_kernel(const float* __restrict__ feat, int off) {
    int idx = off + blockIdx.x * blockDim.x + threadIdx.x;
    if (idx >= BB*VV*HWW) return;
    int p  = idx % HWW;
    int bv = idx / HWW;
    const float* src = feat + (size_t)bv * CC * HWW + p;
    float v[CC];
#pragma unroll
    for (int c = 0; c < CC; c++) v[c] = src[(size_t)c * HWW];
    float4* dst = (float4*)(g_feat_t + ((size_t)bv * HWW + p) * CC);
    dst[0] = make_float4(v[0],  v[1],  v[2],  v[3]);
    dst[1] = make_float4(v[4],  v[5],  v[6],  v[7]);
    dst[2] = make_float4(v[8],  v[9],  v[10], v[11]);
    dst[3] = make_float4(v[12], v[13], v[14], v[15]);
}

// ======================= helpers =======================
struct Coords {
    float fx, fy;
    int jx0, jy0;
    int ix0, ix1, iy0, iy1;
    float m00, m10, m01, m11;
};
__device__ __forceinline__ Coords proj_coords(float dep, float rx, float ry, float rz,
                                              float tx, float ty, float tz) {
    Coords c;
    float X = fmaf(rx, dep, tx);
    float Y = fmaf(ry, dep, ty);
    float Z = fmaf(rz, dep, tz);
    float px = X / Z;            // exact IEEE division (argmax-sensitive)
    float py = Y / Z;
    float x0f = floorf(px), y0f = floorf(py);
    c.fx = px - x0f; c.fy = py - y0f;
    c.jx0 = __float2int_rd(px);
    c.jy0 = __float2int_rd(py);
    bool bx0 = (c.jx0 >= 0)  && (c.jx0 <  WW);
    bool bx1 = (c.jx0 >= -1) && (c.jx0 <  WW-1);
    bool by0 = (c.jy0 >= 0)  && (c.jy0 <  HH);
    bool by1 = (c.jy0 >= -1) && (c.jy0 <  HH-1);
    c.m00 = (bx0 && by0) ? 1.f : 0.f;
    c.m10 = (bx1 && by0) ? 1.f : 0.f;
    c.m01 = (bx0 && by1) ? 1.f : 0.f;
    c.m11 = (bx1 && by1) ? 1.f : 0.f;
    c.ix0 = min(max(c.jx0,     0), WW-1);
    c.ix1 = min(max(c.jx0 + 1, 0), WW-1);
    c.iy0 = min(max(c.jy0,     0), HH-1);
    c.iy1 = min(max(c.jy0 + 1, 0), HH-1);
    return c;
}

__device__ __forceinline__ float full_dot(const float* fp, const float* rp) {
    float part[4];
#pragma unroll
    for (int qq = 0; qq < 4; qq++) {
        float4 f = ((const float4*)fp)[qq];
        float4 r = ((const float4*)rp)[qq];
        part[qq] = fmaf(f.x, r.x, fmaf(f.y, r.y, fmaf(f.z, r.z, f.w * r.w)));
    }
    return (part[0] + part[1]) + (part[2] + part[3]);
}

__device__ __forceinline__ float quarter_dot(const float* fp, int q, float4 rq) {
    float4 f = ((const float4*)fp)[q];
    return fmaf(f.x, rq.x, fmaf(f.y, rq.y, fmaf(f.z, rq.z, f.w * rq.w)));
}

__device__ __forceinline__ float pwl_eval(float s, const float* th, const float* s_ab,
                                          const float* w2r, float fb2) {
    int idx = 0;
#pragma unroll
    for (int i = 0; i < 16; i++) idx += (s > th[i]) ? 1 : 0;
    const float* ab = s_ab + idx * 20;
    float4 A0 = *(const float4*)(ab);
    float4 A1 = *(const float4*)(ab + 4);
    float4 B0 = *(const float4*)(ab + 8);
    float4 B1 = *(const float4*)(ab + 12);
    float ov = fb2;
    ov = fmaf(w2r[0], fmaxf(fmaf(A0.x, s, B0.x), 0.f), ov);
    ov = fmaf(w2r[1], fmaxf(fmaf(A0.y, s, B0.y), 0.f), ov);
    ov = fmaf(w2r[2], fmaxf(fmaf(A0.z, s, B0.z), 0.f), ov);
    ov = fmaf(w2r[3], fmaxf(fmaf(A0.w, s, B0.w), 0.f), ov);
    ov = fmaf(w2r[4], fmaxf(fmaf(A1.x, s, B1.x), 0.f), ov);
    ov = fmaf(w2r[5], fmaxf(fmaf(A1.y, s, B1.y), 0.f), ov);
    ov = fmaf(w2r[6], fmaxf(fmaf(A1.z, s, B1.z), 0.f), ov);
    ov = fmaf(w2r[7], fmaxf(fmaf(A1.w, s, B1.w), 0.f), ov);
    return ov;
}

__device__ __forceinline__ bool frac_safe(float f0, float fL) {
    float lo = fminf(f0, fL), hi = fmaxf(f0, fL);
    return (lo > FRAC_MARGIN) && (hi < 1.f - FRAC_MARGIN);
}

// ======================= fused main: fission (sims -> PWL -> combine) =======================
#define KD (DD/4)   // 12 depths per lane
__global__ void __launch_bounds__(128, 6)
main_kernel(const float* __restrict__ depth_values, float* __restrict__ out) {
    __shared__ __align__(16) float s_ab[17*20];
    __shared__ float s_s0[KD*128];   // [k][tid] sims view0
    __shared__ float s_s1[KD*128];   // [k][tid] sims view1
    for (int i = threadIdx.x; i < 17*20; i += blockDim.x) s_ab[i] = g_pwl_ab[i];
    __syncthreads();

    int tidx = threadIdx.x;
    int tid = blockIdx.x * blockDim.x + tidx;   // NPIX*4
    int q   = tid & 3;
    int pid = tid >> 2;
    int b = pid / HWW;
    int p = pid - b * HWW;
    int h = p / WW;
    int w = p - h * WW;

    const float* refp = g_feat_t + ((size_t)(b*VV + 0) * HWW + p) * CC;
    float4 rq = ((const float4*)refp)[q];

    float rx[2], ry[2], rz[2], tx[2], ty[2], tz[2];
#pragma unroll
    for (int v = 0; v < 2; v++) {
        const float* pr = g_proj + (v*BB + b) * 12;
        float fw = (float)w, fh = (float)h;
        rx[v] = pr[0]*fw + pr[1]*fh + pr[2];
        ry[v] = pr[3]*fw + pr[4]*fh + pr[5];
        rz[v] = pr[6]*fw + pr[7]*fh + pr[8];
        tx[v] = pr[9]; ty[v] = pr[10]; tz[v] = pr[11];
    }
    const float* src0 = g_feat_t + (size_t)(b*VV + 1) * HWW * CC;
    const float* src1 = g_feat_t + (size_t)(b*VV + 2) * HWW * CC;
    const float* dv   = depth_values + (size_t)b * DD * HWW + p;

    // ---- setup: coords at global d=0 and d=DD-1 ----
    float dep0 = __ldg(dv);
    float depL = __ldg(dv + (size_t)(DD-1) * HWW);
    Coords c0A = proj_coords(dep0, rx[0], ry[0], rz[0], tx[0], ty[0], tz[0]);
    Coords c0B = proj_coords(dep0, rx[1], ry[1], rz[1], tx[1], ty[1], tz[1]);
    Coords cLA = proj_coords(depL, rx[0], ry[0], rz[0], tx[0], ty[0], tz[0]);
    Coords cLB = proj_coords(depL, rx[1], ry[1], rz[1], tx[1], ty[1], tz[1]);

    // cooperative corner dots at depth-0 corner (butterflied to all 4 lanes)
    float dA00 = quarter_dot(src0 + ((size_t)(c0A.iy0*WW + c0A.ix0)) * CC, q, rq);
    float dA10 = quarter_dot(src0 + ((size_t)(c0A.iy0*WW + c0A.ix1)) * CC, q, rq);
    float dA01 = quarter_dot(src0 + ((size_t)(c0A.iy1*WW + c0A.ix0)) * CC, q, rq);
    float dA11 = quarter_dot(src0 + ((size_t)(c0A.iy1*WW + c0A.ix1)) * CC, q, rq);
    float dB00 = quarter_dot(src1 + ((size_t)(c0B.iy0*WW + c0B.ix0)) * CC, q, rq);
    float dB10 = quarter_dot(src1 + ((size_t)(c0B.iy0*WW + c0B.ix1)) * CC, q, rq);
    float dB01 = quarter_dot(src1 + ((size_t)(c0B.iy1*WW + c0B.ix0)) * CC, q, rq);
    float dB11 = quarter_dot(src1 + ((size_t)(c0B.iy1*WW + c0B.ix1)) * CC, q, rq);
#pragma unroll
    for (int m = 1; m <= 2; m <<= 1) {
        dA00 += __shfl_xor_sync(0xffffffffu, dA00, m);
        dA10 += __shfl_xor_sync(0xffffffffu, dA10, m);
        dA01 += __shfl_xor_sync(0xffffffffu, dA01, m);
        dA11 += __shfl_xor_sync(0xffffffffu, dA11, m);
        dB00 += __shfl_xor_sync(0xffffffffu, dB00, m);
        dB10 += __shfl_xor_sync(0xffffffffu, dB10, m);
        dB01 += __shfl_xor_sync(0xffffffffu, dB01, m);
        dB11 += __shfl_xor_sync(0xffffffffu, dB11, m);
    }

    bool cornerConst = (c0A.jx0 == cLA.jx0) && (c0A.jy0 == cLA.jy0) &&
                       (c0B.jx0 == cLB.jx0) && (c0B.jy0 == cLB.jy0) &&
                       frac_safe(c0A.fx, cLA.fx) && frac_safe(c0A.fy, cLA.fy) &&
                       frac_safe(c0B.fx, cLB.fx) && frac_safe(c0B.fy, cLB.fy);
    bool interior = (c0A.m00 * c0A.m10 * c0A.m01 * c0A.m11 *
                     c0B.m00 * c0B.m10 * c0B.m01 * c0B.m11) == 1.f;
    bool fast = cornerConst && interior;

    const int STR = 4 * HWW;
    const float* dvp = dv + q * HWW;

    // ---- loop 1: sims only (no PWL state live) ----
    if (fast) {
        float jxfA = (float)c0A.jx0, jyfA = (float)c0A.jy0;
        float jxfB = (float)c0B.jx0, jyfB = (float)c0B.jy0;
        float e10A = dA10 - dA00, e01A = dA01 - dA00;
        float e11A = ((dA00 - dA10) - dA01) + dA11;
        float e10B = dB10 - dB00, e01B = dB01 - dB00;
        float e11B = ((dB00 - dB10) - dB01) + dB11;
#pragma unroll 2
        for (int k = 0; k < KD; k++) {
            float dep = __ldg(dvp + (size_t)k * STR);
            {
                float Z = fmaf(rz[0], dep, tz[0]);
                float X = fmaf(rx[0], dep, tx[0]);
                float Y = fmaf(ry[0], dep, ty[0]);
                float U = fmaf(-jxfA, Z, X);
                float V = fmaf(-jyfA, Z, Y);
                float Z2 = Z * Z;
                float a = fmaf(U, e10A, V * e01A);
                float num = fmaf(dA00, Z2, fmaf(a, Z, (U * V) * e11A));
                s_s0[k*128 + tidx] = (num / Z2) * 0.0625f;
            }
            {
                float Z = fmaf(rz[1], dep, tz[1]);
                float X = fmaf(rx[1], dep, tx[1]);
                float Y = fmaf(ry[1], dep, ty[1]);
                float U = fmaf(-jxfB, Z, X);
                float V = fmaf(-jyfB, Z, Y);
                float Z2 = Z * Z;
                float a = fmaf(U, e10B, V * e01B);
                float num = fmaf(dB00, Z2, fmaf(a, Z, (U * V) * e11B));
                s_s1[k*128 + tidx] = (num / Z2) * 0.0625f;
            }
        }
    } else {
        int cjx0 = c0A.jx0, cjy0 = c0A.jy0, cjx1 = c0B.jx0, cjy1 = c0B.jy0;
#pragma unroll 1
        for (int k = 0; k < KD; k++) {
            float dep = __ldg(dvp + (size_t)k * STR);
            {
                Coords c = proj_coords(dep, rx[0], ry[0], rz[0], tx[0], ty[0], tz[0]);
                if (c.jx0 != cjx0 || c.jy0 != cjy0) {
                    cjx0 = c.jx0; cjy0 = c.jy0;
                    dA00 = full_dot(src0 + ((size_t)(c.iy0*WW + c.ix0)) * CC, refp);
                    dA10 = full_dot(src0 + ((size_t)(c.iy0*WW + c.ix1)) * CC, refp);
                    dA01 = full_dot(src0 + ((size_t)(c.iy1*WW + c.ix0)) * CC, refp);
                    dA11 = full_dot(src0 + ((size_t)(c.iy1*WW + c.ix1)) * CC, refp);
                }
                float w00 = (1.f - c.fx) * (1.f - c.fy) * c.m00;
                float w10 = c.fx * (1.f - c.fy) * c.m10;
                float w01 = (1.f - c.fx) * c.fy * c.m01;
                float w11 = c.fx * c.fy * c.m11;
                s_s0[k*128 + tidx] =
                    fmaf(w00, dA00, fmaf(w10, dA10, fmaf(w01, dA01, w11 * dA11))) * 0.0625f;
            }
            {
                Coords c = proj_coords(dep, rx[1], ry[1], rz[1], tx[1], ty[1], tz[1]);
                if (c.jx0 != cjx1 || c.jy0 != cjy1) {
                    cjx1 = c.jx0; cjy1 = c.jy0;
                    dB00 = full_dot(src1 + ((size_t)(c.iy0*WW + c.ix0)) * CC, refp);
                    dB10 = full_dot(src1 + ((size_t)(c.iy0*WW + c.ix1)) * CC, refp);
                    dB01 = full_dot(src1 + ((size_t)(c.iy1*WW + c.ix0)) * CC, refp);
                    dB11 = full_dot(src1 + ((size_t)(c.iy1*WW + c.ix1)) * CC, refp);
                }
                float w00 = (1.f - c.fx) * (1.f - c.fy) * c.m00;
                float w10 = c.fx * (1.f - c.fy) * c.m10;
                float w01 = (1.f - c.fx) * c.fy * c.m01;
                float w11 = c.fx * c.fy * c.m11;
                s_s1[k*128 + tidx] =
                    fmaf(w00, dB00, fmaf(w10, dB10, fmaf(w01, dB01, w11 * dB11))) * 0.0625f;
            }
        }
    }

    // ---- loop 2: PWL evals (uniform across fast/slow; deep unroll for ILP) ----
    float th[16];
#pragma unroll
    for (int i = 0; i < 16; i++) th[i] = g_pwl_t[i];
    float w2r[8];
#pragma unroll
    for (int j = 0; j < 8; j++) w2r[j] = g_pwl_w2[j];
    float fb2 = g_pwl_w2[8];

    float omax0 = -3.4e38f, omax1 = -3.4e38f;
#pragma unroll 4
    for (int k = 0; k < KD; k++) {
        float sa = s_s0[k*128 + tidx];
        float sb = s_s1[k*128 + tidx];
        omax0 = fmaxf(omax0, pwl_eval(sa, th, s_ab, w2r, fb2));
        omax1 = fmaxf(omax1, pwl_eval(sb, th, s_ab, w2r, fb2));
    }

    omax0 = fmaxf(omax0, __shfl_xor_sync(0xffffffffu, omax0, 1));
    omax0 = fmaxf(omax0, __shfl_xor_sync(0xffffffffu, omax0, 2));
    omax1 = fmaxf(omax1, __shfl_xor_sync(0xffffffffu, omax1, 1));
    omax1 = fmaxf(omax1, __shfl_xor_sync(0xffffffffu, omax1, 2));

    float vw0 = 1.f / (1.f + expf(-omax0));   // exact sigmoid
    float vw1 = 1.f / (1.f + expf(-omax1));
    if (q == 0) {
        out[OFF_VW + (size_t)b * NV * HWW + p] = vw0;
        out[OFF_VW + (size_t)b * NV * HWW + HWW + p] = vw1;
    }

    // ---- loop 3: combine ----
    float denom = 1e-5f + vw0 + vw1;
    float* sop = g_simil + (size_t)b * DD * HWW + p + q * HWW;
#pragma unroll 2
    for (int k = 0; k < KD; k++) {
        float sa = s_s0[k*128 + tidx];
        float sb = s_s1[k*128 + tidx];
        sop[(size_t)k * STR] = (sa * vw0 + sb * vw1) / denom;   // exact division
    }
}

// ======================= 3x3x3 conv + softmax (4 threads per pixel) =======================
#define DQ (DD/4)   // 12
__global__ void conv_softmax_kernel(const float* __restrict__ depth_values, float* __restrict__ out) {
    __shared__ float s_k[28];
    if (threadIdx.x < 28) s_k[threadIdx.x] = g_reg[threadIdx.x];
    __syncthreads();

    int tid = blockIdx.x * blockDim.x + threadIdx.x;   // NPIX*4
    int q   = tid & 3;
    int pid = tid >> 2;
    int b = pid / HWW;
    int p = pid - b * HWW;
    int h = p / WW;
    int w = p - h * WW;
    int base = q * DQ;

    float c[DQ];
    float bias = s_k[27];
#pragma unroll
    for (int d = 0; d < DQ; d++) c[d] = bias;

    bool wl = (w > 0), wr = (w < WW - 1);
#pragma unroll 1
    for (int dpi = 0; dpi < DQ + 2; dpi++) {
        int dp = base - 1 + dpi;
        if ((unsigned)dp >= (unsigned)DD) continue;
        const float* basep = g_simil + (size_t)(b*DD + dp) * HWW;
        float n[9];
#pragma unroll
        for (int dy = 0; dy < 3; dy++) {
            int hh = h + dy - 1;
            bool vy = (unsigned)hh < (unsigned)HH;
            const float* rowp = basep + hh * WW + w;
            n[dy*3+0] = (vy && wl) ? rowp[-1] : 0.f;
            n[dy*3+1] = vy ? rowp[0] : 0.f;
            n[dy*3+2] = (vy && wr) ? rowp[1] : 0.f;
        }
#pragma unroll
        for (int dz = 0; dz < 3; dz++) {
            int od = dp + 1 - dz;
            int lod = od - base;
            if (lod < 0 || lod >= DQ) continue;
            float acc = 0.f;
#pragma unroll
            for (int i = 0; i < 9; i++) acc = fmaf(s_k[dz*9+i], n[i], acc);
            c[lod] += acc;
        }
    }

    float m = c[0]; int am = base;
#pragma unroll
    for (int d = 1; d < DQ; d++) if (c[d] > m) { m = c[d]; am = base + d; }

#pragma unroll
    for (int mask = 1; mask <= 2; mask <<= 1) {
        float mo  = __shfl_xor_sync(0xffffffffu, m, mask);
        int   amo = __shfl_xor_sync(0xffffffffu, am, mask);
        if (mo > m || (mo == m && amo < am)) { m = mo; am = amo; }
    }

    float sum = 0.f;
#pragma unroll
    for (int d = 0; d < DQ; d++) { float e = __expf(c[d] - m); c[d] = e; sum += e; }
    sum += __shfl_xor_sync(0xffffffffu, sum, 1);
    sum += __shfl_xor_sync(0xffffffffu, sum, 2);
    float inv = __fdividef(1.f, sum);

    float* pp = out + OFF_PROB + (size_t)b * DD * HWW + p;
#pragma unroll
    for (int d = 0; d < DQ; d++) pp[(size_t)(base + d) * HWW] = c[d] * inv;

    if (q == 0) {
        out[OFF_DEPTH + pid] = depth_values[(size_t)b * DD * HWW + (size_t)am * HWW + p];
        out[OFF_CONF + pid] = inv;
    }
}

// ======================= launch =======================
extern "C" void kernel_launch(void* const* d_in, const int* in_sizes, int n_in,
                              void* d_out, int out_size) {
    const float* features     = (const float*)d_in[0];
    const float* proj         = (const float*)d_in[1];
    const float* depth_values = (const float*)d_in[2];
    const float* w0 = (const float*)d_in[3];
    const float* g0 = (const float*)d_in[4];
    const float* b0 = (const float*)d_in[5];
    const float* m0 = (const float*)d_in[6];
    const float* v0 = (const float*)d_in[7];
    const float* w1 = (const float*)d_in[8];
    const float* g1 = (const float*)d_in[9];
    const float* b1 = (const float*)d_in[10];
    const float* m1 = (const float*)d_in[11];
    const float* v1 = (const float*)d_in[12];
    const float* w2 = (const float*)d_in[13];
    const float* b2 = (const float*)d_in[14];
    const float* reg_w = (const float*)d_in[15];
    const float* reg_b = (const float*)d_in[16];
    float* out = (float*)d_out;

    const int TN = BB*VV*HWW;
    const int THALF = TN / 2;        // two transpose launches keep main as launch #4 for ncu

    prep_kernel<<<1, 256>>>(proj, w0, g0, b0, m0, v0, w1, g1, b1, m1, v1, w2, b2, reg_w, reg_b);
    transpose_kernel<<<(THALF + 255) / 256, 256>>>(features, 0);
    transpose_kernel<<<(TN - THALF + 255) / 256, 256>>>(features, THALF);
    main_kernel<<<(NPIX*4) / 128, 128>>>(depth_values, out);
    conv_softmax_kernel<<<(NPIX*4 + 127) / 128, 128>>>(depth_values, out);
}

// round 15
// speedup vs baseline: 1.2863x; 1.0292x over previous
#include <cuda_runtime.h>
#include <math.h>
#include <float.h>

// Fixed problem shapes
#define BB 2
#define VV 3
#define CC 16
#define HH 128
#define WW 160
#define DD 48
#define HWW (HH*WW)            // 20480
#define NPIX (BB*HWW)          // 40960
#define BDHW (BB*DD*HWW)       // 1966080
#define NV (VV-1)              // 2 source views

// Output layout
#define OFF_DEPTH 0
#define OFF_CONF  (NPIX)
#define OFF_PROB  (2*NPIX)
#define OFF_VW    (2*NPIX + BDHW)

#define FRAC_MARGIN 2e-4f

// -------- scratch --------
__device__ float g_feat_t[(size_t)BB*VV*HWW*CC];   // [b][v][h][w][c]
__device__ float g_simil[BDHW];
__device__ float g_proj[NV*BB*12];
__device__ float g_reg[28];
__device__ float g_pwl_t[16];
__device__ __align__(16) float g_pwl_ab[17*20];    // row i: alpha[8], beta[8], pad[4]
__device__ float g_pwl_w2[9];

// ======================= prep (fully parallel) =======================
__device__ void compose_proj(const float* p, double* out) {
    const float* E = p;
    const float* K = p + 16;
    for (int i = 0; i < 16; i++) out[i] = (double)E[i];
    for (int r = 0; r < 3; r++)
        for (int c = 0; c < 4; c++) {
            double s = 0.0;
            for (int k = 0; k < 3; k++) s += (double)K[r*4+k] * (double)E[k*4+c];
            out[r*4+c] = s;
        }
}

__global__ void prep_kernel(const float* proj,
                            const float* w0, const float* g0, const float* b0,
                            const float* m0, const float* v0,
                            const float* w1, const float* g1, const float* b1,
                            const float* m1, const float* v1,
                            const float* w2, const float* b2,
                            const float* reg_w, const float* reg_b) {
    __shared__ double sh_comp[BB][VV][16];
    __shared__ double sh_M[BB][4][8];
    __shared__ double sh_refi[BB][16];
    __shared__ double sh_t[16];
    __shared__ float  sh_fw0[16], sh_fc0[16];
    __shared__ float  sh_fw1[8][16], sh_fc1[8];
    __shared__ int    sh_pos[16];

    int tid = threadIdx.x;

    if (tid < BB*VV) {
        int b = tid / VV, v = tid % VV;
        compose_proj(proj + (size_t)(b*VV + v)*2*16, &sh_comp[b][v][0]);
    }
    if (tid >= 32 && tid < 48) {
        int o = tid - 32;
        double s = (double)g0[o] / sqrt((double)v0[o] + 1e-5);
        sh_fw0[o] = (float)((double)w0[o] * s);
        sh_fc0[o] = (float)((double)b0[o] - (double)m0[o] * s);
    }
    if (tid >= 64 && tid < 72) {
        int j = tid - 64;
        double s = (double)g1[j] / sqrt((double)v1[j] + 1e-5);
        for (int o = 0; o < 16; o++)
            sh_fw1[j][o] = (float)((double)w1[j*16+o] * s);
        sh_fc1[j] = (float)((double)b1[j] - (double)m1[j] * s);
        g_pwl_w2[j] = w2[j];
    }
    if (tid >= 96 && tid < 124) {
        int k = tid - 96;
        g_reg[k] = (k < 27) ? reg_w[k] : reg_b[0];
    }
    if (tid == 124) g_pwl_w2[8] = b2[0];
    __syncthreads();

    if (tid < BB*4) {
        int b = tid / 4, r = tid % 4;
        for (int j = 0; j < 4; j++) {
            sh_M[b][r][j]   = sh_comp[b][0][r*4+j];
            sh_M[b][r][4+j] = (r == j) ? 1.0 : 0.0;
        }
    }
    if (tid >= 32 && tid < 48) {
        int o = tid - 32;
        float fw0o = sh_fw0[o];
        sh_t[o] = (fw0o != 0.f) ? (-(double)sh_fc0[o] / (double)fw0o) : DBL_MAX;
    }
    __syncthreads();

    for (int col = 0; col < 4; col++) {
        if (tid < BB) {
            int b = tid;
            double pv = sh_M[b][col][col];
            for (int j = 0; j < 8; j++) sh_M[b][col][j] /= pv;
        }
        __syncthreads();
        if (tid < BB*4) {
            int b = tid / 4, r = tid % 4;
            if (r != col) {
                double f = sh_M[b][r][col];
                for (int j = 0; j < 8; j++) sh_M[b][r][j] -= f * sh_M[b][col][j];
            }
        }
        __syncthreads();
    }
    if (tid < BB*16) {
        int b = tid / 16, e = tid % 16;
        sh_refi[b][e] = sh_M[b][e/4][4 + (e & 3)];
    }
    if (tid >= 32 && tid < 48) {
        int o = tid - 32;
        double tv = sh_t[o];
        int pos = 0;
        for (int oo = 0; oo < 16; oo++) {
            double to = sh_t[oo];
            pos += (to < tv || (to == tv && oo < o)) ? 1 : 0;
        }
        sh_pos[o] = pos;
        g_pwl_t[pos] = (tv >= DBL_MAX) ? FLT_MAX : (float)tv;
    }
    __syncthreads();

    if (tid < NV*BB*12) {
        int e  = tid % 12;
        int vb = tid / 12;
        int b  = vb % BB;
        int v  = 1 + vb / BB;
        int r  = e / 4, c = e & 3;
        double s = 0.0;
        for (int k = 0; k < 4; k++) s += sh_comp[b][v][r*4+k] * sh_refi[b][k*4+c];
        float* dst = g_proj + ((v-1)*BB + b)*12;
        if (c < 3) dst[r*3+c]  = (float)s;
        else       dst[9 + r]  = (float)s;
    }

    if (tid < 17*8) {
        int i = tid / 8;
        int j = tid % 8;
        double alpha = 0.0, beta = (double)sh_fc1[j];
        for (int o = 0; o < 16; o++) {
            bool active;
            float fw0o = sh_fw0[o];
            if (fw0o > 0.f)      active = (sh_pos[o] < i);
            else if (fw0o < 0.f) active = (sh_pos[o] >= i);
            else                 active = (sh_fc0[o] > 0.f);
            if (active) {
                alpha += (double)sh_fw1[j][o] * (double)fw0o;
                beta  += (double)sh_fw1[j][o] * (double)sh_fc0[o];
            }
        }
        g_pwl_ab[i*20 + j]     = (float)alpha;
        g_pwl_ab[i*20 + 8 + j] = (float)beta;
    }
}

// ======================= feature transpose (single launch) =======================
__global__ void transpose_kernel(const float* __restrict__ feat) {
    int idx = blockIdx.x * blockDim.x + threadIdx.x;
    if (idx >= BB*VV*HWW) return;
    int p  = idx % HWW;
    int bv = idx / HWW;
    const float* src = feat + (size_t)bv * CC * HWW + p;
    float v[CC];
#pragma unroll
    for (int c = 0; c < CC; c++) v[c] = src[(size_t)c * HWW];
    float4* dst = (float4*)(g_feat_t + ((size_t)bv * HWW + p) * CC);
    dst[0] = make_float4(v[0],  v[1],  v[2],  v[3]);
    dst[1] = make_float4(v[4],  v[5],  v[6],  v[7]);
    dst[2] = make_float4(v[8],  v[9],  v[10], v[11]);
    dst[3] = make_float4(v[12], v[13], v[14], v[15]);
}

// ======================= helpers =======================
struct Coords {
    float fx, fy;
    int jx0, jy0;
    int ix0, ix1, iy0, iy1;
    float m00, m10, m01, m11;
};
__device__ __forceinline__ Coords proj_coords(float dep, float rx, float ry, float rz,
                                              float tx, float ty, float tz) {
    Coords c;
    float X = fmaf(rx, dep, tx);
    float Y = fmaf(ry, dep, ty);
    float Z = fmaf(rz, dep, tz);
    float px = X / Z;            // exact IEEE division (argmax-sensitive)
    float py = Y / Z;
    float x0f = floorf(px), y0f = floorf(py);
    c.fx = px - x0f; c.fy = py - y0f;
    c.jx0 = __float2int_rd(px);
    c.jy0 = __float2int_rd(py);
    bool bx0 = (c.jx0 >= 0)  && (c.jx0 <  WW);
    bool bx1 = (c.jx0 >= -1) && (c.jx0 <  WW-1);
    bool by0 = (c.jy0 >= 0)  && (c.jy0 <  HH);
    bool by1 = (c.jy0 >= -1) && (c.jy0 <  HH-1);
    c.m00 = (bx0 && by0) ? 1.f : 0.f;
    c.m10 = (bx1 && by0) ? 1.f : 0.f;
    c.m01 = (bx0 && by1) ? 1.f : 0.f;
    c.m11 = (bx1 && by1) ? 1.f : 0.f;
    c.ix0 = min(max(c.jx0,     0), WW-1);
    c.ix1 = min(max(c.jx0 + 1, 0), WW-1);
    c.iy0 = min(max(c.jy0,     0), HH-1);
    c.iy1 = min(max(c.jy0 + 1, 0), HH-1);
    return c;
}

__device__ __forceinline__ float full_dot(const float* fp, const float* rp) {
    float part[4];
#pragma unroll
    for (int qq = 0; qq < 4; qq++) {
        float4 f = ((const float4*)fp)[qq];
        float4 r = ((const float4*)rp)[qq];
        part[qq] = fmaf(f.x, r.x, fmaf(f.y, r.y, fmaf(f.z, r.z, f.w * r.w)));
    }
    return (part[0] + part[1]) + (part[2] + part[3]);
}

__device__ __forceinline__ float quarter_dot(const float* fp, int q, float4 rq) {
    float4 f = ((const float4*)fp)[q];
    return fmaf(f.x, rq.x, fmaf(f.y, rq.y, fmaf(f.z, rq.z, f.w * rq.w)));
}

// Binary-search interval index: rank of s in sorted th[16], range [0,16].
// 4-level tree gives rank min(r,15); the final (s > th[15]) term supplies
// the 17th value. Equal to #{i: s > th[i]} for ALL s (FLT_MAX sorts last).
__device__ __forceinline__ int pwl_idx(float s, const float* th) {
    bool b3 = s > th[7];
    float t2 = b3 ? th[11] : th[3];
    bool b2 = s > t2;
    float t1a = b2 ? th[5]  : th[1];
    float t1b = b2 ? th[13] : th[9];
    float t1  = b3 ? t1b : t1a;
    bool b1 = s > t1;
    float t0a = b1 ? th[2]  : th[0];
    float t0b = b1 ? th[6]  : th[4];
    float t0c = b1 ? th[10] : th[8];
    float t0d = b1 ? th[14] : th[12];
    float t0ab = b2 ? t0b : t0a;
    float t0cd = b2 ? t0d : t0c;
    float t0 = b3 ? t0cd : t0ab;
    bool b0 = s > t0;
    int idx = ((int)b3 << 3) | ((int)b2 << 2) | ((int)b1 << 1) | (int)b0;
    idx += (s > th[15]) ? 1 : 0;   // rank-16 case (missing in R14 -> bug)
    return idx;
}

__device__ __forceinline__ float pwl_eval(float s, const float* th, const float* s_ab,
                                          const float* w2r, float fb2) {
    int idx = pwl_idx(s, th);
    const float* ab = s_ab + idx * 20;
    float4 A0 = *(const float4*)(ab);
    float4 A1 = *(const float4*)(ab + 4);
    float4 B0 = *(const float4*)(ab + 8);
    float4 B1 = *(const float4*)(ab + 12);
    float ov = fb2;
    ov = fmaf(w2r[0], fmaxf(fmaf(A0.x, s, B0.x), 0.f), ov);
    ov = fmaf(w2r[1], fmaxf(fmaf(A0.y, s, B0.y), 0.f), ov);
    ov = fmaf(w2r[2], fmaxf(fmaf(A0.z, s, B0.z), 0.f), ov);
    ov = fmaf(w2r[3], fmaxf(fmaf(A0.w, s, B0.w), 0.f), ov);
    ov = fmaf(w2r[4], fmaxf(fmaf(A1.x, s, B1.x), 0.f), ov);
    ov = fmaf(w2r[5], fmaxf(fmaf(A1.y, s, B1.y), 0.f), ov);
    ov = fmaf(w2r[6], fmaxf(fmaf(A1.z, s, B1.z), 0.f), ov);
    ov = fmaf(w2r[7], fmaxf(fmaf(A1.w, s, B1.w), 0.f), ov);
    return ov;
}

__device__ __forceinline__ bool frac_safe(float f0, float fL) {
    float lo = fminf(f0, fL), hi = fmaxf(f0, fL);
    return (lo > FRAC_MARGIN) && (hi < 1.f - FRAC_MARGIN);
}

// ======================= fused main: fission (sims -> PWL -> combine) =======================
#define KD (DD/4)   // 12 depths per lane
__global__ void __launch_bounds__(128, 6)
main_kernel(const float* __restrict__ depth_values, float* __restrict__ out) {
    __shared__ __align__(16) float s_ab[17*20];
    __shared__ float s_s0[KD*128];   // [k][tid] sims view0
    __shared__ float s_s1[KD*128];   // [k][tid] sims view1
    for (int i = threadIdx.x; i < 17*20; i += blockDim.x) s_ab[i] = g_pwl_ab[i];
    __syncthreads();

    int tidx = threadIdx.x;
    int tid = blockIdx.x * blockDim.x + tidx;   // NPIX*4
    int q   = tid & 3;
    int pid = tid >> 2;
    int b = pid / HWW;
    int p = pid - b * HWW;
    int h = p / WW;
    int w = p - h * WW;

    const float* refp = g_feat_t + ((size_t)(b*VV + 0) * HWW + p) * CC;
    float4 rq = ((const float4*)refp)[q];

    float rx[2], ry[2], rz[2], tx[2], ty[2], tz[2];
#pragma unroll
    for (int v = 0; v < 2; v++) {
        const float* pr = g_proj + (v*BB + b) * 12;
        float fw = (float)w, fh = (float)h;
        rx[v] = pr[0]*fw + pr[1]*fh + pr[2];
        ry[v] = pr[3]*fw + pr[4]*fh + pr[5];
        rz[v] = pr[6]*fw + pr[7]*fh + pr[8];
        tx[v] = pr[9]; ty[v] = pr[10]; tz[v] = pr[11];
    }
    const float* src0 = g_feat_t + (size_t)(b*VV + 1) * HWW * CC;
    const float* src1 = g_feat_t + (size_t)(b*VV + 2) * HWW * CC;
    const float* dv   = depth_values + (size_t)b * DD * HWW + p;

    // ---- setup: coords at global d=0 and d=DD-1 ----
    float dep0 = __ldg(dv);
    float depL = __ldg(dv + (size_t)(DD-1) * HWW);
    Coords c0A = proj_coords(dep0, rx[0], ry[0], rz[0], tx[0], ty[0], tz[0]);
    Coords c0B = proj_coords(dep0, rx[1], ry[1], rz[1], tx[1], ty[1], tz[1]);
    Coords cLA = proj_coords(depL, rx[0], ry[0], rz[0], tx[0], ty[0], tz[0]);
    Coords cLB = proj_coords(depL, rx[1], ry[1], rz[1], tx[1], ty[1], tz[1]);

    // cooperative corner dots at depth-0 corner (butterflied to all 4 lanes)
    float dA00 = quarter_dot(src0 + ((size_t)(c0A.iy0*WW + c0A.ix0)) * CC, q, rq);
    float dA10 = quarter_dot(src0 + ((size_t)(c0A.iy0*WW + c0A.ix1)) * CC, q, rq);
    float dA01 = quarter_dot(src0 + ((size_t)(c0A.iy1*WW + c0A.ix0)) * CC, q, rq);
    float dA11 = quarter_dot(src0 + ((size_t)(c0A.iy1*WW + c0A.ix1)) * CC, q, rq);
    float dB00 = quarter_dot(src1 + ((size_t)(c0B.iy0*WW + c0B.ix0)) * CC, q, rq);
    float dB10 = quarter_dot(src1 + ((size_t)(c0B.iy0*WW + c0B.ix1)) * CC, q, rq);
    float dB01 = quarter_dot(src1 + ((size_t)(c0B.iy1*WW + c0B.ix0)) * CC, q, rq);
    float dB11 = quarter_dot(src1 + ((size_t)(c0B.iy1*WW + c0B.ix1)) * CC, q, rq);
#pragma unroll
    for (int m = 1; m <= 2; m <<= 1) {
        dA00 += __shfl_xor_sync(0xffffffffu, dA00, m);
        dA10 += __shfl_xor_sync(0xffffffffu, dA10, m);
        dA01 += __shfl_xor_sync(0xffffffffu, dA01, m);
        dA11 += __shfl_xor_sync(0xffffffffu, dA11, m);
        dB00 += __shfl_xor_sync(0xffffffffu, dB00, m);
        dB10 += __shfl_xor_sync(0xffffffffu, dB10, m);
        dB01 += __shfl_xor_sync(0xffffffffu, dB01, m);
        dB11 += __shfl_xor_sync(0xffffffffu, dB11, m);
    }

    bool cornerConst = (c0A.jx0 == cLA.jx0) && (c0A.jy0 == cLA.jy0) &&
                       (c0B.jx0 == cLB.jx0) && (c0B.jy0 == cLB.jy0) &&
                       frac_safe(c0A.fx, cLA.fx) && frac_safe(c0A.fy, cLA.fy) &&
                       frac_safe(c0B.fx, cLB.fx) && frac_safe(c0B.fy, cLB.fy);
    bool interior = (c0A.m00 * c0A.m10 * c0A.m01 * c0A.m11 *
                     c0B.m00 * c0B.m10 * c0B.m01 * c0B.m11) == 1.f;
    bool fast = cornerConst && interior;

    const int STR = 4 * HWW;
    const float* dvp = dv + q * HWW;

    // ---- loop 1: sims only ----
    if (fast) {
        float jxfA = (float)c0A.jx0, jyfA = (float)c0A.jy0;
        float jxfB = (float)c0B.jx0, jyfB = (float)c0B.jy0;
        float e10A = dA10 - dA00, e01A = dA01 - dA00;
        float e11A = ((dA00 - dA10) - dA01) + dA11;
        float e10B = dB10 - dB00, e01B = dB01 - dB00;
        float e11B = ((dB00 - dB10) - dB01) + dB11;
#pragma unroll 2
        for (int k = 0; k < KD; k++) {
            float dep = __ldg(dvp + (size_t)k * STR);
            {
                float Z = fmaf(rz[0], dep, tz[0]);
                float X = fmaf(rx[0], dep, tx[0]);
                float Y = fmaf(ry[0], dep, ty[0]);
                float U = fmaf(-jxfA, Z, X);
                float V = fmaf(-jyfA, Z, Y);
                float Z2 = Z * Z;
                float a = fmaf(U, e10A, V * e01A);
                float num = fmaf(dA00, Z2, fmaf(a, Z, (U * V) * e11A));
                s_s0[k*128 + tidx] = (num / Z2) * 0.0625f;
            }
            {
                float Z = fmaf(rz[1], dep, tz[1]);
                float X = fmaf(rx[1], dep, tx[1]);
                float Y = fmaf(ry[1], dep, ty[1]);
                float U = fmaf(-jxfB, Z, X);
                float V = fmaf(-jyfB, Z, Y);
                float Z2 = Z * Z;
                float a = fmaf(U, e10B, V * e01B);
                float num = fmaf(dB00, Z2, fmaf(a, Z, (U * V) * e11B));
                s_s1[k*128 + tidx] = (num / Z2) * 0.0625f;
            }
        }
    } else {
        int cjx0 = c0A.jx0, cjy0 = c0A.jy0, cjx1 = c0B.jx0, cjy1 = c0B.jy0;
#pragma unroll 1
        for (int k = 0; k < KD; k++) {
            float dep = __ldg(dvp + (size_t)k * STR);
            {
                Coords c = proj_coords(dep, rx[0], ry[0], rz[0], tx[0], ty[0], tz[0]);
                if (c.jx0 != cjx0 || c.jy0 != cjy0) {
                    cjx0 = c.jx0; cjy0 = c.jy0;
                    dA00 = full_dot(src0 + ((size_t)(c.iy0*WW + c.ix0)) * CC, refp);
                    dA10 = full_dot(src0 + ((size_t)(c.iy0*WW + c.ix1)) * CC, refp);
                    dA01 = full_dot(src0 + ((size_t)(c.iy1*WW + c.ix0)) * CC, refp);
                    dA11 = full_dot(src0 + ((size_t)(c.iy1*WW + c.ix1)) * CC, refp);
                }
                float w00 = (1.f - c.fx) * (1.f - c.fy) * c.m00;
                float w10 = c.fx * (1.f - c.fy) * c.m10;
                float w01 = (1.f - c.fx) * c.fy * c.m01;
                float w11 = c.fx * c.fy * c.m11;
                s_s0[k*128 + tidx] =
                    fmaf(w00, dA00, fmaf(w10, dA10, fmaf(w01, dA01, w11 * dA11))) * 0.0625f;
            }
            {
                Coords c = proj_coords(dep, rx[1], ry[1], rz[1], tx[1], ty[1], tz[1]);
                if (c.jx0 != cjx1 || c.jy0 != cjy1) {
                    cjx1 = c.jx0; cjy1 = c.jy0;
                    dB00 = full_dot(src1 + ((size_t)(c.iy0*WW + c.ix0)) * CC, refp);
                    dB10 = full_dot(src1 + ((size_t)(c.iy0*WW + c.ix1)) * CC, refp);
                    dB01 = full_dot(src1 + ((size_t)(c.iy1*WW + c.ix0)) * CC, refp);
                    dB11 = full_dot(src1 + ((size_t)(c.iy1*WW + c.ix1)) * CC, refp);
                }
                float w00 = (1.f - c.fx) * (1.f - c.fy) * c.m00;
                float w10 = c.fx * (1.f - c.fy) * c.m10;
                float w01 = (1.f - c.fx) * c.fy * c.m01;
                float w11 = c.fx * c.fy * c.m11;
                s_s1[k*128 + tidx] =
                    fmaf(w00, dB00, fmaf(w10, dB10, fmaf(w01, dB01, w11 * dB11))) * 0.0625f;
            }
        }
    }

    // ---- loop 2: PWL evals (uniform across fast/slow; deep unroll for ILP) ----
    float th[16];
#pragma unroll
    for (int i = 0; i < 16; i++) th[i] = g_pwl_t[i];
    float w2r[8];
#pragma unroll
    for (int j = 0; j < 8; j++) w2r[j] = g_pwl_w2[j];
    float fb2 = g_pwl_w2[8];

    float omax0 = -3.4e38f, omax1 = -3.4e38f;
#pragma unroll 4
    for (int k = 0; k < KD; k++) {
        float sa = s_s0[k*128 + tidx];
        float sb = s_s1[k*128 + tidx];
        omax0 = fmaxf(omax0, pwl_eval(sa, th, s_ab, w2r, fb2));
        omax1 = fmaxf(omax1, pwl_eval(sb, th, s_ab, w2r, fb2));
    }

    omax0 = fmaxf(omax0, __shfl_xor_sync(0xffffffffu, omax0, 1));
    omax0 = fmaxf(omax0, __shfl_xor_sync(0xffffffffu, omax0, 2));
    omax1 = fmaxf(omax1, __shfl_xor_sync(0xffffffffu, omax1, 1));
    omax1 = fmaxf(omax1, __shfl_xor_sync(0xffffffffu, omax1, 2));

    float vw0 = 1.f / (1.f + expf(-omax0));   // exact sigmoid
    float vw1 = 1.f / (1.f + expf(-omax1));
    if (q == 0) {
        out[OFF_VW + (size_t)b * NV * HWW + p] = vw0;
        out[OFF_VW + (size_t)b * NV * HWW + HWW + p] = vw1;
    }

    // ---- loop 3: combine ----
    float denom = 1e-5f + vw0 + vw1;
    float* sop = g_simil + (size_t)b * DD * HWW + p + q * HWW;
#pragma unroll 2
    for (int k = 0; k < KD; k++) {
        float sa = s_s0[k*128 + tidx];
        float sb = s_s1[k*128 + tidx];
        sop[(size_t)k * STR] = (sa * vw0 + sb * vw1) / denom;   // exact division
    }
}

// ======================= 3x3x3 conv + softmax (4 threads per pixel) =======================
#define DQ (DD/4)   // 12
__global__ void conv_softmax_kernel(const float* __restrict__ depth_values, float* __restrict__ out) {
    __shared__ float s_k[28];
    if (threadIdx.x < 28) s_k[threadIdx.x] = g_reg[threadIdx.x];
    __syncthreads();

    int tid = blockIdx.x * blockDim.x + threadIdx.x;   // NPIX*4
    int q   = tid & 3;
    int pid = tid >> 2;
    int b = pid / HWW;
    int p = pid - b * HWW;
    int h = p / WW;
    int w = p - h * WW;
    int base = q * DQ;

    float c[DQ];
    float bias = s_k[27];
#pragma unroll
    for (int d = 0; d < DQ; d++) c[d] = bias;

    bool wl = (w > 0), wr = (w < WW - 1);
#pragma unroll 1
    for (int dpi = 0; dpi < DQ + 2; dpi++) {
        int dp = base - 1 + dpi;
        if ((unsigned)dp >= (unsigned)DD) continue;
        const float* basep = g_simil + (size_t)(b*DD + dp) * HWW;
        float n[9];
#pragma unroll
        for (int dy = 0; dy < 3; dy++) {
            int hh = h + dy - 1;
            bool vy = (unsigned)hh < (unsigned)HH;
            const float* rowp = basep + hh * WW + w;
            n[dy*3+0] = (vy && wl) ? rowp[-1] : 0.f;
            n[dy*3+1] = vy ? rowp[0] : 0.f;
            n[dy*3+2] = (vy && wr) ? rowp[1] : 0.f;
        }
#pragma unroll
        for (int dz = 0; dz < 3; dz++) {
            int od = dp + 1 - dz;
            int lod = od - base;
            if (lod < 0 || lod >= DQ) continue;
            float acc = 0.f;
#pragma unroll
            for (int i = 0; i < 9; i++) acc = fmaf(s_k[dz*9+i], n[i], acc);
            c[lod] += acc;
        }
    }

    float m = c[0]; int am = base;
#pragma unroll
    for (int d = 1; d < DQ; d++) if (c[d] > m) { m = c[d]; am = base + d; }

#pragma unroll
    for (int mask = 1; mask <= 2; mask <<= 1) {
        float mo  = __shfl_xor_sync(0xffffffffu, m, mask);
        int   amo = __shfl_xor_sync(0xffffffffu, am, mask);
        if (mo > m || (mo == m && amo < am)) { m = mo; am = amo; }
    }

    float sum = 0.f;
#pragma unroll
    for (int d = 0; d < DQ; d++) { float e = __expf(c[d] - m); c[d] = e; sum += e; }
    sum += __shfl_xor_sync(0xffffffffu, sum, 1);
    sum += __shfl_xor_sync(0xffffffffu, sum, 2);
    float inv = __fdividef(1.f, sum);

    float* pp = out + OFF_PROB + (size_t)b * DD * HWW + p;
#pragma unroll
    for (int d = 0; d < DQ; d++) pp[(size_t)(base + d) * HWW] = c[d] * inv;

    if (q == 0) {
        out[OFF_DEPTH + pid] = depth_values[(size_t)b * DD * HWW + (size_t)am * HWW + p];
        out[OFF_CONF + pid] = inv;
    }
}

// ======================= launch =======================
extern "C" void kernel_launch(void* const* d_in, const int* in_sizes, int n_in,
                              void* d_out, int out_size) {
    const float* features     = (const float*)d_in[0];
    const float* proj         = (const float*)d_in[1];
    const float* depth_values = (const float*)d_in[2];
    const float* w0 = (const float*)d_in[3];
    const float* g0 = (const float*)d_in[4];
    const float* b0 = (const float*)d_in[5];
    const float* m0 = (const float*)d_in[6];
    const float* v0 = (const float*)d_in[7];
    const float* w1 = (const float*)d_in[8];
    const float* g1 = (const float*)d_in[9];
    const float* b1 = (const float*)d_in[10];
    const float* m1 = (const float*)d_in[11];
    const float* v1 = (const float*)d_in[12];
    const float* w2 = (const float*)d_in[13];
    const float* b2 = (const float*)d_in[14];
    const float* reg_w = (const float*)d_in[15];
    const float* reg_b = (const float*)d_in[16];
    float* out = (float*)d_out;

    // 4 launches; conv_softmax is launch #4 -> profiled next round
    prep_kernel<<<1, 256>>>(proj, w0, g0, b0, m0, v0, w1, g1, b1, m1, v1, w2, b2, reg_w, reg_b);
    transpose_kernel<<<(BB*VV*HWW + 255) / 256, 256>>>(features);
    main_kernel<<<(NPIX*4) / 128, 128>>>(depth_values, out);
    conv_softmax_kernel<<<(NPIX*4 + 127) / 128, 128>>>(depth_values, out);
}

// round 16
// speedup vs baseline: 1.4788x; 1.1497x over previous
#include <cuda_runtime.h>
#include <math.h>
#include <float.h>

// Fixed problem shapes
#define BB 2
#define VV 3
#define CC 16
#define HH 128
#define WW 160
#define DD 48
#define HWW (HH*WW)            // 20480
#define NPIX (BB*HWW)          // 40960
#define BDHW (BB*DD*HWW)       // 1966080
#define NV (VV-1)              // 2 source views

// Output layout
#define OFF_DEPTH 0
#define OFF_CONF  (NPIX)
#define OFF_PROB  (2*NPIX)
#define OFF_VW    (2*NPIX + BDHW)

#define FRAC_MARGIN 2e-4f

// -------- scratch --------
__device__ float g_feat_t[(size_t)BB*VV*HWW*CC];   // [b][v][h][w][c]
__device__ float g_simil[BDHW];
__device__ float g_proj[NV*BB*12];
__device__ float g_reg[28];
__device__ float g_pwl_t[16];
__device__ __align__(16) float g_pwl_ab[17*20];    // row i: alpha[8], beta[8], pad[4]
__device__ float g_pwl_w2[9];

// ======================= prep (fully parallel) =======================
__device__ void compose_proj(const float* p, double* out) {
    const float* E = p;
    const float* K = p + 16;
    for (int i = 0; i < 16; i++) out[i] = (double)E[i];
    for (int r = 0; r < 3; r++)
        for (int c = 0; c < 4; c++) {
            double s = 0.0;
            for (int k = 0; k < 3; k++) s += (double)K[r*4+k] * (double)E[k*4+c];
            out[r*4+c] = s;
        }
}

__global__ void prep_kernel(const float* proj,
                            const float* w0, const float* g0, const float* b0,
                            const float* m0, const float* v0,
                            const float* w1, const float* g1, const float* b1,
                            const float* m1, const float* v1,
                            const float* w2, const float* b2,
                            const float* reg_w, const float* reg_b) {
    __shared__ double sh_comp[BB][VV][16];
    __shared__ double sh_M[BB][4][8];
    __shared__ double sh_refi[BB][16];
    __shared__ double sh_t[16];
    __shared__ float  sh_fw0[16], sh_fc0[16];
    __shared__ float  sh_fw1[8][16], sh_fc1[8];
    __shared__ int    sh_pos[16];

    int tid = threadIdx.x;

    if (tid < BB*VV) {
        int b = tid / VV, v = tid % VV;
        compose_proj(proj + (size_t)(b*VV + v)*2*16, &sh_comp[b][v][0]);
    }
    if (tid >= 32 && tid < 48) {
        int o = tid - 32;
        double s = (double)g0[o] / sqrt((double)v0[o] + 1e-5);
        sh_fw0[o] = (float)((double)w0[o] * s);
        sh_fc0[o] = (float)((double)b0[o] - (double)m0[o] * s);
    }
    if (tid >= 64 && tid < 72) {
        int j = tid - 64;
        double s = (double)g1[j] / sqrt((double)v1[j] + 1e-5);
        for (int o = 0; o < 16; o++)
            sh_fw1[j][o] = (float)((double)w1[j*16+o] * s);
        sh_fc1[j] = (float)((double)b1[j] - (double)m1[j] * s);
        g_pwl_w2[j] = w2[j];
    }
    if (tid >= 96 && tid < 124) {
        int k = tid - 96;
        g_reg[k] = (k < 27) ? reg_w[k] : reg_b[0];
    }
    if (tid == 124) g_pwl_w2[8] = b2[0];
    __syncthreads();

    if (tid < BB*4) {
        int b = tid / 4, r = tid % 4;
        for (int j = 0; j < 4; j++) {
            sh_M[b][r][j]   = sh_comp[b][0][r*4+j];
            sh_M[b][r][4+j] = (r == j) ? 1.0 : 0.0;
        }
    }
    if (tid >= 32 && tid < 48) {
        int o = tid - 32;
        float fw0o = sh_fw0[o];
        sh_t[o] = (fw0o != 0.f) ? (-(double)sh_fc0[o] / (double)fw0o) : DBL_MAX;
    }
    __syncthreads();

    for (int col = 0; col < 4; col++) {
        if (tid < BB) {
            int b = tid;
            double pv = sh_M[b][col][col];
            for (int j = 0; j < 8; j++) sh_M[b][col][j] /= pv;
        }
        __syncthreads();
        if (tid < BB*4) {
            int b = tid / 4, r = tid % 4;
            if (r != col) {
                double f = sh_M[b][r][col];
                for (int j = 0; j < 8; j++) sh_M[b][r][j] -= f * sh_M[b][col][j];
            }
        }
        __syncthreads();
    }
    if (tid < BB*16) {
        int b = tid / 16, e = tid % 16;
        sh_refi[b][e] = sh_M[b][e/4][4 + (e & 3)];
    }
    if (tid >= 32 && tid < 48) {
        int o = tid - 32;
        double tv = sh_t[o];
        int pos = 0;
        for (int oo = 0; oo < 16; oo++) {
            double to = sh_t[oo];
            pos += (to < tv || (to == tv && oo < o)) ? 1 : 0;
        }
        sh_pos[o] = pos;
        g_pwl_t[pos] = (tv >= DBL_MAX) ? FLT_MAX : (float)tv;
    }
    __syncthreads();

    if (tid < NV*BB*12) {
        int e  = tid % 12;
        int vb = tid / 12;
        int b  = vb % BB;
        int v  = 1 + vb / BB;
        int r  = e / 4, c = e & 3;
        double s = 0.0;
        for (int k = 0; k < 4; k++) s += sh_comp[b][v][r*4+k] * sh_refi[b][k*4+c];
        float* dst = g_proj + ((v-1)*BB + b)*12;
        if (c < 3) dst[r*3+c]  = (float)s;
        else       dst[9 + r]  = (float)s;
    }

    if (tid < 17*8) {
        int i = tid / 8;
        int j = tid % 8;
        double alpha = 0.0, beta = (double)sh_fc1[j];
        for (int o = 0; o < 16; o++) {
            bool active;
            float fw0o = sh_fw0[o];
            if (fw0o > 0.f)      active = (sh_pos[o] < i);
            else if (fw0o < 0.f) active = (sh_pos[o] >= i);
            else                 active = (sh_fc0[o] > 0.f);
            if (active) {
                alpha += (double)sh_fw1[j][o] * (double)fw0o;
                beta  += (double)sh_fw1[j][o] * (double)sh_fc0[o];
            }
        }
        g_pwl_ab[i*20 + j]     = (float)alpha;
        g_pwl_ab[i*20 + 8 + j] = (float)beta;
    }
}

// ======================= feature transpose (single launch) =======================
__global__ void transpose_kernel(const float* __restrict__ feat) {
    int idx = blockIdx.x * blockDim.x + threadIdx.x;
    if (idx >= BB*VV*HWW) return;
    int p  = idx % HWW;
    int bv = idx / HWW;
    const float* src = feat + (size_t)bv * CC * HWW + p;
    float v[CC];
#pragma unroll
    for (int c = 0; c < CC; c++) v[c] = src[(size_t)c * HWW];
    float4* dst = (float4*)(g_feat_t + ((size_t)bv * HWW + p) * CC);
    dst[0] = make_float4(v[0],  v[1],  v[2],  v[3]);
    dst[1] = make_float4(v[4],  v[5],  v[6],  v[7]);
    dst[2] = make_float4(v[8],  v[9],  v[10], v[11]);
    dst[3] = make_float4(v[12], v[13], v[14], v[15]);
}

// ======================= helpers =======================
struct Coords {
    float fx, fy;
    int jx0, jy0;
    int ix0, ix1, iy0, iy1;
    float m00, m10, m01, m11;
};
__device__ __forceinline__ Coords proj_coords(float dep, float rx, float ry, float rz,
                                              float tx, float ty, float tz) {
    Coords c;
    float X = fmaf(rx, dep, tx);
    float Y = fmaf(ry, dep, ty);
    float Z = fmaf(rz, dep, tz);
    float px = X / Z;            // exact IEEE division (argmax-sensitive)
    float py = Y / Z;
    float x0f = floorf(px), y0f = floorf(py);
    c.fx = px - x0f; c.fy = py - y0f;
    c.jx0 = __float2int_rd(px);
    c.jy0 = __float2int_rd(py);
    bool bx0 = (c.jx0 >= 0)  && (c.jx0 <  WW);
    bool bx1 = (c.jx0 >= -1) && (c.jx0 <  WW-1);
    bool by0 = (c.jy0 >= 0)  && (c.jy0 <  HH);
    bool by1 = (c.jy0 >= -1) && (c.jy0 <  HH-1);
    c.m00 = (bx0 && by0) ? 1.f : 0.f;
    c.m10 = (bx1 && by0) ? 1.f : 0.f;
    c.m01 = (bx0 && by1) ? 1.f : 0.f;
    c.m11 = (bx1 && by1) ? 1.f : 0.f;
    c.ix0 = min(max(c.jx0,     0), WW-1);
    c.ix1 = min(max(c.jx0 + 1, 0), WW-1);
    c.iy0 = min(max(c.jy0,     0), HH-1);
    c.iy1 = min(max(c.jy0 + 1, 0), HH-1);
    return c;
}

__device__ __forceinline__ float full_dot(const float* fp, const float* rp) {
    float part[4];
#pragma unroll
    for (int qq = 0; qq < 4; qq++) {
        float4 f = ((const float4*)fp)[qq];
        float4 r = ((const float4*)rp)[qq];
        part[qq] = fmaf(f.x, r.x, fmaf(f.y, r.y, fmaf(f.z, r.z, f.w * r.w)));
    }
    return (part[0] + part[1]) + (part[2] + part[3]);
}

__device__ __forceinline__ float quarter_dot(const float* fp, int q, float4 rq) {
    float4 f = ((const float4*)fp)[q];
    return fmaf(f.x, rq.x, fmaf(f.y, rq.y, fmaf(f.z, rq.z, f.w * rq.w)));
}

// Binary-search interval index: rank of s in sorted th[16], range [0,16].
__device__ __forceinline__ int pwl_idx(float s, const float* th) {
    bool b3 = s > th[7];
    float t2 = b3 ? th[11] : th[3];
    bool b2 = s > t2;
    float t1a = b2 ? th[5]  : th[1];
    float t1b = b2 ? th[13] : th[9];
    float t1  = b3 ? t1b : t1a;
    bool b1 = s > t1;
    float t0a = b1 ? th[2]  : th[0];
    float t0b = b1 ? th[6]  : th[4];
    float t0c = b1 ? th[10] : th[8];
    float t0d = b1 ? th[14] : th[12];
    float t0ab = b2 ? t0b : t0a;
    float t0cd = b2 ? t0d : t0c;
    float t0 = b3 ? t0cd : t0ab;
    bool b0 = s > t0;
    int idx = ((int)b3 << 3) | ((int)b2 << 2) | ((int)b1 << 1) | (int)b0;
    idx += (s > th[15]) ? 1 : 0;   // rank-16 case
    return idx;
}

__device__ __forceinline__ float pwl_eval(float s, const float* th, const float* s_ab,
                                          const float* w2r, float fb2) {
    int idx = pwl_idx(s, th);
    const float* ab = s_ab + idx * 20;
    float4 A0 = *(const float4*)(ab);
    float4 A1 = *(const float4*)(ab + 4);
    float4 B0 = *(const float4*)(ab + 8);
    float4 B1 = *(const float4*)(ab + 12);
    float ov = fb2;
    ov = fmaf(w2r[0], fmaxf(fmaf(A0.x, s, B0.x), 0.f), ov);
    ov = fmaf(w2r[1], fmaxf(fmaf(A0.y, s, B0.y), 0.f), ov);
    ov = fmaf(w2r[2], fmaxf(fmaf(A0.z, s, B0.z), 0.f), ov);
    ov = fmaf(w2r[3], fmaxf(fmaf(A0.w, s, B0.w), 0.f), ov);
    ov = fmaf(w2r[4], fmaxf(fmaf(A1.x, s, B1.x), 0.f), ov);
    ov = fmaf(w2r[5], fmaxf(fmaf(A1.y, s, B1.y), 0.f), ov);
    ov = fmaf(w2r[6], fmaxf(fmaf(A1.z, s, B1.z), 0.f), ov);
    ov = fmaf(w2r[7], fmaxf(fmaf(A1.w, s, B1.w), 0.f), ov);
    return ov;
}

__device__ __forceinline__ bool frac_safe(float f0, float fL) {
    float lo = fminf(f0, fL), hi = fmaxf(f0, fL);
    return (lo > FRAC_MARGIN) && (hi < 1.f - FRAC_MARGIN);
}

// ======================= fused main: fission (sims -> PWL -> combine) =======================
#define KD (DD/4)   // 12 depths per lane
__global__ void __launch_bounds__(128, 6)
main_kernel(const float* __restrict__ depth_values, float* __restrict__ out) {
    __shared__ __align__(16) float s_ab[17*20];
    __shared__ float s_s0[KD*128];   // [k][tid] sims view0
    __shared__ float s_s1[KD*128];   // [k][tid] sims view1
    for (int i = threadIdx.x; i < 17*20; i += blockDim.x) s_ab[i] = g_pwl_ab[i];
    __syncthreads();

    int tidx = threadIdx.x;
    int tid = blockIdx.x * blockDim.x + tidx;   // NPIX*4
    int q   = tid & 3;
    int pid = tid >> 2;
    int b = pid / HWW;
    int p = pid - b * HWW;
    int h = p / WW;
    int w = p - h * WW;

    const float* refp = g_feat_t + ((size_t)(b*VV + 0) * HWW + p) * CC;
    float4 rq = ((const float4*)refp)[q];

    float rx[2], ry[2], rz[2], tx[2], ty[2], tz[2];
#pragma unroll
    for (int v = 0; v < 2; v++) {
        const float* pr = g_proj + (v*BB + b) * 12;
        float fw = (float)w, fh = (float)h;
        rx[v] = pr[0]*fw + pr[1]*fh + pr[2];
        ry[v] = pr[3]*fw + pr[4]*fh + pr[5];
        rz[v] = pr[6]*fw + pr[7]*fh + pr[8];
        tx[v] = pr[9]; ty[v] = pr[10]; tz[v] = pr[11];
    }
    const float* src0 = g_feat_t + (size_t)(b*VV + 1) * HWW * CC;
    const float* src1 = g_feat_t + (size_t)(b*VV + 2) * HWW * CC;
    const float* dv   = depth_values + (size_t)b * DD * HWW + p;

    // ---- setup: coords at global d=0 and d=DD-1 ----
    float dep0 = __ldg(dv);
    float depL = __ldg(dv + (size_t)(DD-1) * HWW);
    Coords c0A = proj_coords(dep0, rx[0], ry[0], rz[0], tx[0], ty[0], tz[0]);
    Coords c0B = proj_coords(dep0, rx[1], ry[1], rz[1], tx[1], ty[1], tz[1]);
    Coords cLA = proj_coords(depL, rx[0], ry[0], rz[0], tx[0], ty[0], tz[0]);
    Coords cLB = proj_coords(depL, rx[1], ry[1], rz[1], tx[1], ty[1], tz[1]);

    // cooperative corner dots at depth-0 corner (butterflied to all 4 lanes)
    float dA00 = quarter_dot(src0 + ((size_t)(c0A.iy0*WW + c0A.ix0)) * CC, q, rq);
    float dA10 = quarter_dot(src0 + ((size_t)(c0A.iy0*WW + c0A.ix1)) * CC, q, rq);
    float dA01 = quarter_dot(src0 + ((size_t)(c0A.iy1*WW + c0A.ix0)) * CC, q, rq);
    float dA11 = quarter_dot(src0 + ((size_t)(c0A.iy1*WW + c0A.ix1)) * CC, q, rq);
    float dB00 = quarter_dot(src1 + ((size_t)(c0B.iy0*WW + c0B.ix0)) * CC, q, rq);
    float dB10 = quarter_dot(src1 + ((size_t)(c0B.iy0*WW + c0B.ix1)) * CC, q, rq);
    float dB01 = quarter_dot(src1 + ((size_t)(c0B.iy1*WW + c0B.ix0)) * CC, q, rq);
    float dB11 = quarter_dot(src1 + ((size_t)(c0B.iy1*WW + c0B.ix1)) * CC, q, rq);
#pragma unroll
    for (int m = 1; m <= 2; m <<= 1) {
        dA00 += __shfl_xor_sync(0xffffffffu, dA00, m);
        dA10 += __shfl_xor_sync(0xffffffffu, dA10, m);
        dA01 += __shfl_xor_sync(0xffffffffu, dA01, m);
        dA11 += __shfl_xor_sync(0xffffffffu, dA11, m);
        dB00 += __shfl_xor_sync(0xffffffffu, dB00, m);
        dB10 += __shfl_xor_sync(0xffffffffu, dB10, m);
        dB01 += __shfl_xor_sync(0xffffffffu, dB01, m);
        dB11 += __shfl_xor_sync(0xffffffffu, dB11, m);
    }

    bool cornerConst = (c0A.jx0 == cLA.jx0) && (c0A.jy0 == cLA.jy0) &&
                       (c0B.jx0 == cLB.jx0) && (c0B.jy0 == cLB.jy0) &&
                       frac_safe(c0A.fx, cLA.fx) && frac_safe(c0A.fy, cLA.fy) &&
                       frac_safe(c0B.fx, cLB.fx) && frac_safe(c0B.fy, cLB.fy);
    bool interior = (c0A.m00 * c0A.m10 * c0A.m01 * c0A.m11 *
                     c0B.m00 * c0B.m10 * c0B.m01 * c0B.m11) == 1.f;
    bool fast = cornerConst && interior;

    const int STR = 4 * HWW;
    const float* dvp = dv + q * HWW;

    // ---- loop 1: sims only ----
    if (fast) {
        float jxfA = (float)c0A.jx0, jyfA = (float)c0A.jy0;
        float jxfB = (float)c0B.jx0, jyfB = (float)c0B.jy0;
        float e10A = dA10 - dA00, e01A = dA01 - dA00;
        float e11A = ((dA00 - dA10) - dA01) + dA11;
        float e10B = dB10 - dB00, e01B = dB01 - dB00;
        float e11B = ((dB00 - dB10) - dB01) + dB11;
#pragma unroll 2
        for (int k = 0; k < KD; k++) {
            float dep = __ldg(dvp + (size_t)k * STR);
            {
                float Z = fmaf(rz[0], dep, tz[0]);
                float X = fmaf(rx[0], dep, tx[0]);
                float Y = fmaf(ry[0], dep, ty[0]);
                float U = fmaf(-jxfA, Z, X);
                float V = fmaf(-jyfA, Z, Y);
                float Z2 = Z * Z;
                float a = fmaf(U, e10A, V * e01A);
                float num = fmaf(dA00, Z2, fmaf(a, Z, (U * V) * e11A));
                s_s0[k*128 + tidx] = (num / Z2) * 0.0625f;
            }
            {
                float Z = fmaf(rz[1], dep, tz[1]);
                float X = fmaf(rx[1], dep, tx[1]);
                float Y = fmaf(ry[1], dep, ty[1]);
                float U = fmaf(-jxfB, Z, X);
                float V = fmaf(-jyfB, Z, Y);
                float Z2 = Z * Z;
                float a = fmaf(U, e10B, V * e01B);
                float num = fmaf(dB00, Z2, fmaf(a, Z, (U * V) * e11B));
                s_s1[k*128 + tidx] = (num / Z2) * 0.0625f;
            }
        }
    } else {
        int cjx0 = c0A.jx0, cjy0 = c0A.jy0, cjx1 = c0B.jx0, cjy1 = c0B.jy0;
#pragma unroll 1
        for (int k = 0; k < KD; k++) {
            float dep = __ldg(dvp + (size_t)k * STR);
            {
                Coords c = proj_coords(dep, rx[0], ry[0], rz[0], tx[0], ty[0], tz[0]);
                if (c.jx0 != cjx0 || c.jy0 != cjy0) {
                    cjx0 = c.jx0; cjy0 = c.jy0;
                    dA00 = full_dot(src0 + ((size_t)(c.iy0*WW + c.ix0)) * CC, refp);
                    dA10 = full_dot(src0 + ((size_t)(c.iy0*WW + c.ix1)) * CC, refp);
                    dA01 = full_dot(src0 + ((size_t)(c.iy1*WW + c.ix0)) * CC, refp);
                    dA11 = full_dot(src0 + ((size_t)(c.iy1*WW + c.ix1)) * CC, refp);
                }
                float w00 = (1.f - c.fx) * (1.f - c.fy) * c.m00;
                float w10 = c.fx * (1.f - c.fy) * c.m10;
                float w01 = (1.f - c.fx) * c.fy * c.m01;
                float w11 = c.fx * c.fy * c.m11;
                s_s0[k*128 + tidx] =
                    fmaf(w00, dA00, fmaf(w10, dA10, fmaf(w01, dA01, w11 * dA11))) * 0.0625f;
            }
            {
                Coords c = proj_coords(dep, rx[1], ry[1], rz[1], tx[1], ty[1], tz[1]);
                if (c.jx0 != cjx1 || c.jy0 != cjy1) {
                    cjx1 = c.jx0; cjy1 = c.jy0;
                    dB00 = full_dot(src1 + ((size_t)(c.iy0*WW + c.ix0)) * CC, refp);
                    dB10 = full_dot(src1 + ((size_t)(c.iy0*WW + c.ix1)) * CC, refp);
                    dB01 = full_dot(src1 + ((size_t)(c.iy1*WW + c.ix0)) * CC, refp);
                    dB11 = full_dot(src1 + ((size_t)(c.iy1*WW + c.ix1)) * CC, refp);
                }
                float w00 = (1.f - c.fx) * (1.f - c.fy) * c.m00;
                float w10 = c.fx * (1.f - c.fy) * c.m10;
                float w01 = (1.f - c.fx) * c.fy * c.m01;
                float w11 = c.fx * c.fy * c.m11;
                s_s1[k*128 + tidx] =
                    fmaf(w00, dB00, fmaf(w10, dB10, fmaf(w01, dB01, w11 * dB11))) * 0.0625f;
            }
        }
    }

    // ---- loop 2: PWL evals ----
    float th[16];
#pragma unroll
    for (int i = 0; i < 16; i++) th[i] = g_pwl_t[i];
    float w2r[8];
#pragma unroll
    for (int j = 0; j < 8; j++) w2r[j] = g_pwl_w2[j];
    float fb2 = g_pwl_w2[8];

    float omax0 = -3.4e38f, omax1 = -3.4e38f;
#pragma unroll 4
    for (int k = 0; k < KD; k++) {
        float sa = s_s0[k*128 + tidx];
        float sb = s_s1[k*128 + tidx];
        omax0 = fmaxf(omax0, pwl_eval(sa, th, s_ab, w2r, fb2));
        omax1 = fmaxf(omax1, pwl_eval(sb, th, s_ab, w2r, fb2));
    }

    omax0 = fmaxf(omax0, __shfl_xor_sync(0xffffffffu, omax0, 1));
    omax0 = fmaxf(omax0, __shfl_xor_sync(0xffffffffu, omax0, 2));
    omax1 = fmaxf(omax1, __shfl_xor_sync(0xffffffffu, omax1, 1));
    omax1 = fmaxf(omax1, __shfl_xor_sync(0xffffffffu, omax1, 2));

    float vw0 = 1.f / (1.f + expf(-omax0));   // exact sigmoid
    float vw1 = 1.f / (1.f + expf(-omax1));
    if (q == 0) {
        out[OFF_VW + (size_t)b * NV * HWW + p] = vw0;
        out[OFF_VW + (size_t)b * NV * HWW + HWW + p] = vw1;
    }

    // ---- loop 3: combine ----
    float denom = 1e-5f + vw0 + vw1;
    float* sop = g_simil + (size_t)b * DD * HWW + p + q * HWW;
#pragma unroll 2
    for (int k = 0; k < KD; k++) {
        float sa = s_s0[k*128 + tidx];
        float sb = s_s1[k*128 + tidx];
        sop[(size_t)k * STR] = (sa * vw0 + sb * vw1) / denom;   // exact division
    }
}

// ======================= 3x3x3 conv + softmax (4 threads/pixel, ALU-lean) =======================
#define DQ (DD/4)   // 12
__global__ void conv_softmax_kernel(const float* __restrict__ depth_values, float* __restrict__ out) {
    __shared__ float s_k[28];
    if (threadIdx.x < 28) s_k[threadIdx.x] = g_reg[threadIdx.x];
    __syncthreads();

    int tid = blockIdx.x * blockDim.x + threadIdx.x;   // NPIX*4
    int q   = tid & 3;
    int pid = tid >> 2;
    int b = pid / HWW;
    int p = pid - b * HWW;
    int h = p / WW;
    int w = p - h * WW;
    int base = q * DQ;

    float c[DQ];
    float bias = s_k[27];
#pragma unroll
    for (int d = 0; d < DQ; d++) c[d] = bias;

    // hoisted invariants
    bool wl = (w > 0), wr = (w < WW - 1);
    bool vy0 = (h > 0), vy2 = (h < HH - 1);
    int ro0 = (h-1) * WW + w;       // may be invalid; loads predicated by vy0
    int ro1 = h * WW + w;
    int ro2 = (h+1) * WW + w;

    // plane pointer for dp = base-1 (never dereferenced when out of range)
    const float* plane = g_simil + (size_t)b * DD * HWW + (ptrdiff_t)(base - 1) * HWW;

#pragma unroll
    for (int dpi = 0; dpi < DQ + 2; dpi++) {
        int dp = base - 1 + dpi;
        if ((unsigned)dp < (unsigned)DD) {
            float n[9];
            n[0] = (vy0 && wl) ? plane[ro0 - 1] : 0.f;
            n[1] = vy0 ? plane[ro0] : 0.f;
            n[2] = (vy0 && wr) ? plane[ro0 + 1] : 0.f;
            n[3] = wl ? plane[ro1 - 1] : 0.f;
            n[4] = plane[ro1];
            n[5] = wr ? plane[ro1 + 1] : 0.f;
            n[6] = (vy2 && wl) ? plane[ro2 - 1] : 0.f;
            n[7] = vy2 ? plane[ro2] : 0.f;
            n[8] = (vy2 && wr) ? plane[ro2 + 1] : 0.f;

            // three 9-tap dots (same FMA order as before)
            float a0 = 0.f, a1 = 0.f, a2 = 0.f;
#pragma unroll
            for (int i = 0; i < 9; i++) {
                a0 = fmaf(s_k[i],      n[i], a0);
                a1 = fmaf(s_k[9 + i],  n[i], a1);
                a2 = fmaf(s_k[18 + i], n[i], a2);
            }
            // od = dp+1 (dz=0, a0), dp (dz=1, a1), dp-1 (dz=2, a2)
            int l1 = dp - base;
            int l0 = l1 + 1;
            int l2 = l1 - 1;
            if (l0 >= 0 && l0 < DQ) c[l0] += a0;
            if (l1 >= 0 && l1 < DQ) c[l1] += a1;
            if (l2 >= 0 && l2 < DQ) c[l2] += a2;
        }
        plane += HWW;
    }

    float m = c[0]; int am = base;
#pragma unroll
    for (int d = 1; d < DQ; d++) if (c[d] > m) { m = c[d]; am = base + d; }

#pragma unroll
    for (int mask = 1; mask <= 2; mask <<= 1) {
        float mo  = __shfl_xor_sync(0xffffffffu, m, mask);
        int   amo = __shfl_xor_sync(0xffffffffu, am, mask);
        if (mo > m || (mo == m && amo < am)) { m = mo; am = amo; }
    }

    float sum = 0.f;
#pragma unroll
    for (int d = 0; d < DQ; d++) { float e = __expf(c[d] - m); c[d] = e; sum += e; }
    sum += __shfl_xor_sync(0xffffffffu, sum, 1);
    sum += __shfl_xor_sync(0xffffffffu, sum, 2);
    float inv = __fdividef(1.f, sum);

    float* pp = out + OFF_PROB + (size_t)b * DD * HWW + p;
#pragma unroll
    for (int d = 0; d < DQ; d++) pp[(size_t)(base + d) * HWW] = c[d] * inv;

    if (q == 0) {
        out[OFF_DEPTH + pid] = depth_values[(size_t)b * DD * HWW + (size_t)am * HWW + p];
        out[OFF_CONF + pid] = inv;
    }
}

// ======================= launch =======================
extern "C" void kernel_launch(void* const* d_in, const int* in_sizes, int n_in,
                              void* d_out, int out_size) {
    const float* features     = (const float*)d_in[0];
    const float* proj         = (const float*)d_in[1];
    const float* depth_values = (const float*)d_in[2];
    const float* w0 = (const float*)d_in[3];
    const float* g0 = (const float*)d_in[4];
    const float* b0 = (const float*)d_in[5];
    const float* m0 = (const float*)d_in[6];
    const float* v0 = (const float*)d_in[7];
    const float* w1 = (const float*)d_in[8];
    const float* g1 = (const float*)d_in[9];
    const float* b1 = (const float*)d_in[10];
    const float* m1 = (const float*)d_in[11];
    const float* v1 = (const float*)d_in[12];
    const float* w2 = (const float*)d_in[13];
    const float* b2 = (const float*)d_in[14];
    const float* reg_w = (const float*)d_in[15];
    const float* reg_b = (const float*)d_in[16];
    float* out = (float*)d_out;

    prep_kernel<<<1, 256>>>(proj, w0, g0, b0, m0, v0, w1, g1, b1, m1, v1, w2, b2, reg_w, reg_b);
    transpose_kernel<<<(BB*VV*HWW + 255) / 256, 256>>>(features);
    main_kernel<<<(NPIX*4) / 128, 128>>>(depth_values, out);
    conv_softmax_kernel<<<(NPIX*4 + 127) / 128, 128>>>(depth_values, out);
}